// round 6
// baseline (speedup 1.0000x reference)
#include <cuda_runtime.h>
#include <cuda_fp16.h>
#include <math.h>
#include <stdint.h>

// Problem constants
#define Bb   2
#define Ss   2048
#define Dd   1024
#define Hh   16
#define DKk  64
#define AUGC 192              // [time(64) | Re(64) | Im(64)]
#define ECOLS 576             // fp16 ext: [time 3x64 | freq 3x128]
#define BHh  (Bb * Hh)        // 32
#define Mm   (Bb * Ss)        // 4096
#define NPART 32              // softmax partials per row: 8 ntiles x 4 wn-warps

// Scratch
__device__ float   g_Qaug[(size_t)BHh * Ss * AUGC];
__device__ float   g_Kaug[(size_t)BHh * Ss * AUGC];
__device__ __half  g_Qe16[(size_t)BHh * Ss * ECOLS];
__device__ __half  g_Ke16[(size_t)BHh * Ss * ECOLS];
__device__ float   g_Vt  [(size_t)BHh * DKk * Ss];
__device__ float   g_O   [(size_t)Mm * Dd];
__device__ float   g_pmax[(size_t)BHh * Ss * NPART];
__device__ float   g_psum[(size_t)BHh * Ss * NPART];
__device__ float   g_rowm[(size_t)BHh * Ss];
__device__ float   g_rowz[(size_t)BHh * Ss];
__device__ float2  g_twid[1024];

// ---------------------------------------------------------------------------
// Twiddle init (fp64-accurate)
// ---------------------------------------------------------------------------
__global__ void twiddle_init_k() {
    int t = blockIdx.x * blockDim.x + threadIdx.x;
    if (t < 1024) {
        double ang = -2.0 * 3.14159265358979323846 * (double)t / 2048.0;
        double s, c;
        sincos(ang, &s, &c);
        g_twid[t] = make_float2((float)c, (float)s);
    }
}

// ---------------------------------------------------------------------------
// Generic fp32 SGEMM (known-good): C = A * W^T (+bias)
// ---------------------------------------------------------------------------
template<int NG, int MODE>
__global__ __launch_bounds__(256)
void sgemm_k(const float* __restrict__ A, size_t saZ,
             const float* __restrict__ W, size_t swZ,
             const float* __restrict__ bias,
             float* __restrict__ C, size_t scB1, size_t scB2, int Hdiv,
             int K, int lda, int ldw, int ldc)
{
    const int BM = 128, BK = 8;
    const int BN = 64 * NG;
    __shared__ float As[2][BK][BM];
    __shared__ float Ws[2][BK][BN];

    int z = blockIdx.z;
    const float* Ab = A + (size_t)z * saZ;
    const float* Wb = W + (size_t)z * swZ;
    size_t cbase = (size_t)(z / Hdiv) * scB1 + (size_t)(z % Hdiv) * scB2;

    int m0 = blockIdx.y * BM;
    int n0 = blockIdx.x * BN;
    int tid = threadIdx.x;
    int tx = tid & 15, ty = tid >> 4;
    int lr = tid >> 1;
    int lc = (tid & 1) * 4;

    float acc[8][4 * NG];
#pragma unroll
    for (int i = 0; i < 8; i++)
#pragma unroll
        for (int j = 0; j < 4 * NG; j++) acc[i][j] = 0.f;

    auto ldst = [&](int buf, int kt) {
        float4 av = *(const float4*)(Ab + (size_t)(m0 + lr) * lda + kt + lc);
        As[buf][lc + 0][lr] = av.x;
        As[buf][lc + 1][lr] = av.y;
        As[buf][lc + 2][lr] = av.z;
        As[buf][lc + 3][lr] = av.w;
        if (NG == 2 || tid < 128) {
            float4 wv = *(const float4*)(Wb + (size_t)(n0 + lr) * ldw + kt + lc);
            Ws[buf][lc + 0][lr] = wv.x;
            Ws[buf][lc + 1][lr] = wv.y;
            Ws[buf][lc + 2][lr] = wv.z;
            Ws[buf][lc + 3][lr] = wv.w;
        }
    };

    ldst(0, 0);
    __syncthreads();

    int nk = K / BK;
    for (int t = 0; t < nk; t++) {
        int buf = t & 1;
        if (t + 1 < nk) ldst(buf ^ 1, (t + 1) * BK);
#pragma unroll
        for (int kk = 0; kk < BK; kk++) {
            float a[8], b[4 * NG];
            *(float4*)&a[0] = *(const float4*)&As[buf][kk][ty * 4];
            *(float4*)&a[4] = *(const float4*)&As[buf][kk][ty * 4 + 64];
            *(float4*)&b[0] = *(const float4*)&Ws[buf][kk][tx * 4];
            if (NG == 2)
                *(float4*)&b[4] = *(const float4*)&Ws[buf][kk][tx * 4 + 64];
#pragma unroll
            for (int i = 0; i < 8; i++)
#pragma unroll
                for (int j = 0; j < 4 * NG; j++)
                    acc[i][j] = fmaf(a[i], b[j], acc[i][j]);
        }
        __syncthreads();
    }

#pragma unroll
    for (int gi = 0; gi < 2; gi++) {
#pragma unroll
        for (int i = 0; i < 4; i++) {
            int m = m0 + ty * 4 + gi * 64 + i;
#pragma unroll
            for (int gj = 0; gj < NG; gj++) {
                int n = n0 + tx * 4 + gj * 64;
                float4 v;
                v.x = acc[gi * 4 + i][gj * 4 + 0];
                v.y = acc[gi * 4 + i][gj * 4 + 1];
                v.z = acc[gi * 4 + i][gj * 4 + 2];
                v.w = acc[gi * 4 + i][gj * 4 + 3];
                if (bias) {
                    v.x += bias[n + 0]; v.y += bias[n + 1];
                    v.z += bias[n + 2]; v.w += bias[n + 3];
                }
                if (MODE == 0) {
                    *(float4*)(C + cbase + (size_t)m * ldc + n) = v;
                } else if (MODE == 1) {
                    int bb = m >> 11, s = m & 2047;
                    int hh = n >> 6,  d = n & 63;
                    *(float4*)(C + ((size_t)((bb * 16 + hh) * 2048 + s)) * AUGC + d) = v;
                } else {
                    int bb = m >> 11, s = m & 2047;
                    int hh = n >> 6,  d = n & 63;
                    float* cp = C + ((size_t)(bb * 16 + hh) * 64 + d) * 2048 + s;
                    cp[0 * 2048] = v.x; cp[1 * 2048] = v.y;
                    cp[2 * 2048] = v.z; cp[3 * 2048] = v.w;
                }
            }
        }
    }
}

// ---------------------------------------------------------------------------
// FFT (known-good)
// ---------------------------------------------------------------------------
__global__ __launch_bounds__(256)
void fft_k(float* qaug, float* kaug, const float* twp, const float* fwp)
{
    __shared__ float  sr[2][2048];
    __shared__ float  si[2][2048];
    __shared__ float2 tw[1024];

    int bh     = blockIdx.x;
    int tensor = blockIdx.y;
    int dk0    = blockIdx.z * 2;
    float* base = (tensor == 0 ? qaug : kaug) + (size_t)bh * Ss * AUGC;
    int tid = threadIdx.x;

    for (int t = tid; t < 1024; t += 256) tw[t] = g_twid[t];

    for (int idx = tid; idx < 2 * Ss; idx += 256) {
        int l = idx & 1;
        int s = idx >> 1;
        float v = base[(size_t)s * AUGC + dk0 + l];
        int rs = __brev((unsigned)s) >> 21;
        sr[l][rs] = v;
        si[l][rs] = 0.f;
    }
    __syncthreads();

    for (int len = 2; len <= 2048; len <<= 1) {
        int half = len >> 1;
        int step = 2048 / len;
        for (int idx = tid; idx < 2048; idx += 256) {
            int l   = idx >> 10;
            int bix = idx & 1023;
            int grp = bix / half;
            int pos = bix - grp * half;
            int i0 = grp * len + pos;
            int i1 = i0 + half;
            float2 w = tw[pos * step];
            float xr = sr[l][i1], xi = si[l][i1];
            float tr = xr * w.x - xi * w.y;
            float ti = xr * w.y + xi * w.x;
            float ur = sr[l][i0], ui = si[l][i0];
            sr[l][i0] = ur + tr;  si[l][i0] = ui + ti;
            sr[l][i1] = ur - tr;  si[l][i1] = ui - ti;
        }
        __syncthreads();
    }

    float ft, ff;
    if (tensor == 0) { ft = twp[0] * 0.125f; ff = fwp[0] * 0.125f; }
    else             { ft = 1.f;             ff = 1.f; }

    for (int idx = tid; idx < 2 * Ss; idx += 256) {
        int l = idx & 1;
        int s = idx >> 1;
        size_t o = (size_t)s * AUGC + dk0 + l;
        if (tensor == 0) base[o] *= ft;
        base[o + 64]  = sr[l][s] * ff;
        base[o + 128] = si[l][s] * ff;
    }
}

// ---------------------------------------------------------------------------
// Convert aug (192 f32) -> fp16x2 ext (576 fp16):
//   cols [0,192)  : time  [h|l|h] (Q) / [h|h|l] (K), span 64
//   cols [192,576): freq  [h|l|h] (Q) / [h|h|l] (K), span 128
// ---------------------------------------------------------------------------
__device__ __forceinline__ uint32_t packh2(__half a, __half b) {
    __half2 p = __halves2half2(a, b);
    return *reinterpret_cast<uint32_t*>(&p);
}
template<int QMODE>
__global__ __launch_bounds__(256)
void convert16_k(const float* __restrict__ src, __half* __restrict__ dst)
{
    size_t i4 = (size_t)blockIdx.x * 256 + threadIdx.x;   // 48 float4 per row
    size_t row = i4 / 48;
    int c4 = (int)(i4 % 48);
    float4 x = ((const float4*)src)[i4];

    __half hx = __float2half_rn(x.x), hy = __float2half_rn(x.y);
    __half hz = __float2half_rn(x.z), hw = __float2half_rn(x.w);
    __half lx = __float2half_rn(x.x - __half2float(hx));
    __half ly = __float2half_rn(x.y - __half2float(hy));
    __half lz = __float2half_rn(x.z - __half2float(hz));
    __half lw = __float2half_rn(x.w - __half2float(hw));

    uint2 H, L;
    H.x = packh2(hx, hy); H.y = packh2(hz, hw);
    L.x = packh2(lx, ly); L.y = packh2(lz, lw);

    __half* drow = dst + row * ECOLS;
    int base, f, span;
    if (c4 < 16) { base = 0;   f = c4 * 4;      span = 64;  }
    else         { base = 192; f = c4 * 4 - 64; span = 128; }

    *(uint2*)(drow + base + f) = H;
    if (QMODE) {   // Q: [h | l | h]
        *(uint2*)(drow + base + span + f)     = L;
        *(uint2*)(drow + base + 2 * span + f) = H;
    } else {       // K: [h | h | l]
        *(uint2*)(drow + base + span + f)     = H;
        *(uint2*)(drow + base + 2 * span + f) = L;
    }
}

// ---------------------------------------------------------------------------
// fp16 mma scores kernel. CTA tile 128x256, 8 warps @64x64, K chunks of 32.
// EPI=0 (freq pass): KOFF=192, NCH=12, grid (8, 9, 32); stores raw freq to
//   attn for rows <=1024 and the conjugate mirror to rows 2048-r.
// EPI=1 (time pass): KOFF=0, NCH=6, grid (8, 16, 32); adds the staged freq,
//   stores combined logits, emits per-(row,ntile,wn) softmax partials.
// dyn smem = 61440 B
// ---------------------------------------------------------------------------
#define A16B (128 * 80)
#define B16B (256 * 80)

__device__ __forceinline__ void mma_fp16(float c[4], const uint32_t a[4],
                                         const uint32_t b[2]) {
    asm volatile(
        "mma.sync.aligned.m16n8k16.row.col.f32.f16.f16.f32 "
        "{%0,%1,%2,%3}, {%4,%5,%6,%7}, {%8,%9}, {%0,%1,%2,%3};"
        : "+f"(c[0]), "+f"(c[1]), "+f"(c[2]), "+f"(c[3])
        : "r"(a[0]), "r"(a[1]), "r"(a[2]), "r"(a[3]), "r"(b[0]), "r"(b[1]));
}

template<int KOFF, int NCH, int EPI>
__global__ __launch_bounds__(256, 1)
void scores16_k(const __half* __restrict__ Qe, const __half* __restrict__ Ke,
                float* __restrict__ attn,
                float* __restrict__ pmax, float* __restrict__ psum)
{
    extern __shared__ char smc[];

    const int tid  = threadIdx.x;
    const int wid  = tid >> 5;
    const int lane = tid & 31;
    const int g    = lane >> 2;
    const int tig  = lane & 3;
    const int wm   = wid >> 2;
    const int wn   = wid & 3;

    const int ntile = blockIdx.x;
    const int mtile = blockIdx.y;
    const int bh    = blockIdx.z;
    const int m0 = mtile * 128;
    const int n0 = ntile * 256;

    const __half* Ag = Qe + ((size_t)bh * Ss + m0) * ECOLS + KOFF;
    const __half* Bg = Ke + ((size_t)bh * Ss + n0) * ECOLS + KOFF;

    const int lrow = tid >> 3;
    const int t8   = tid & 7;

    float acc[4][8][4];
#pragma unroll
    for (int mf = 0; mf < 4; mf++)
#pragma unroll
        for (int nf = 0; nf < 8; nf++)
#pragma unroll
            for (int j = 0; j < 4; j++) acc[mf][nf][j] = 0.f;

    uint2 ra[4], rb[8];
    auto ldg = [&](int c) {
#pragma unroll
        for (int i = 0; i < 4; i++)
            ra[i] = *(const uint2*)(Ag + (size_t)(lrow + i * 32) * ECOLS + c * 32 + t8 * 4);
#pragma unroll
        for (int i = 0; i < 8; i++)
            rb[i] = *(const uint2*)(Bg + (size_t)(lrow + i * 32) * ECOLS + c * 32 + t8 * 4);
    };
    auto sts = [&](int b) {
        char* a16 = smc + b * A16B;
#pragma unroll
        for (int i = 0; i < 4; i++)
            *(uint2*)(a16 + (lrow + i * 32) * 80 + t8 * 8) = ra[i];
        char* b16 = smc + 2 * A16B + b * B16B;
#pragma unroll
        for (int i = 0; i < 8; i++)
            *(uint2*)(b16 + (lrow + i * 32) * 80 + t8 * 8) = rb[i];
    };

    ldg(0);
    sts(0);
    __syncthreads();

    for (int c = 0; c < NCH; c++) {
        int buf = c & 1;
        if (c + 1 < NCH) ldg(c + 1);

        const char* a16 = smc + buf * A16B + (wm * 64) * 80;
        const char* b16 = smc + 2 * A16B + buf * B16B + (wn * 64) * 80;
#pragma unroll
        for (int st = 0; st < 2; st++) {
            int kb = st * 32;
            uint32_t bfr[8][2];
#pragma unroll
            for (int nf = 0; nf < 8; nf++) {
                const char* br = b16 + (nf * 8 + g) * 80 + kb + tig * 4;
                bfr[nf][0] = *(const uint32_t*)br;
                bfr[nf][1] = *(const uint32_t*)(br + 16);
            }
#pragma unroll
            for (int mf = 0; mf < 4; mf++) {
                const char* ar = a16 + (mf * 16 + g) * 80 + kb + tig * 4;
                uint32_t afr[4];
                afr[0] = *(const uint32_t*)ar;
                afr[1] = *(const uint32_t*)(ar + 8 * 80);
                afr[2] = *(const uint32_t*)(ar + 16);
                afr[3] = *(const uint32_t*)(ar + 8 * 80 + 16);
#pragma unroll
                for (int nf = 0; nf < 8; nf++)
                    mma_fp16(acc[mf][nf], afr, bfr[nf]);
            }
        }
        if (c + 1 < NCH) sts(buf ^ 1);
        __syncthreads();
    }

    const int cbase = n0 + wn * 64 + tig * 2;

    if (EPI == 0) {
        // freq pass: raw freq -> rows <=1024 direct; conjugate mirror for 1..1023
#pragma unroll
        for (int mf = 0; mf < 4; mf++) {
            int r0 = m0 + wm * 64 + mf * 16 + g;
#pragma unroll
            for (int hf = 0; hf < 2; hf++) {
                int r = r0 + hf * 8;
                if (r <= 1024) {
                    float* arow = attn + ((size_t)bh << 22) + (size_t)r * Ss;
#pragma unroll
                    for (int nf = 0; nf < 8; nf++)
                        *(float2*)(arow + cbase + nf * 8) =
                            make_float2(acc[mf][nf][hf * 2], acc[mf][nf][hf * 2 + 1]);
                }
                if (r >= 1 && r <= 1023) {
                    int mq = 2048 - r;
                    float* mrow = attn + ((size_t)bh << 22) + (size_t)mq * Ss;
#pragma unroll
                    for (int nf = 0; nf < 8; nf++) {
                        int c0 = cbase + nf * 8;
                        mrow[(2048 - c0) & 2047]     = acc[mf][nf][hf * 2];
                        mrow[(2048 - c0 - 1) & 2047] = acc[mf][nf][hf * 2 + 1];
                    }
                }
            }
        }
    } else {
        // time pass: add staged freq, store combined logits, softmax partials
#pragma unroll
        for (int mf = 0; mf < 4; mf++) {
            int row0 = m0 + wm * 64 + mf * 16 + g;
            float* arow  = attn + ((size_t)bh << 22) + (size_t)row0 * Ss + cbase;
            float* arow8 = arow + 8 * Ss;
#pragma unroll
            for (int nf = 0; nf < 8; nf++) {
                float2 f0 = *(float2*)(arow + nf * 8);
                acc[mf][nf][0] += f0.x; acc[mf][nf][1] += f0.y;
                float2 f8 = *(float2*)(arow8 + nf * 8);
                acc[mf][nf][2] += f8.x; acc[mf][nf][3] += f8.y;
            }

            float mx0 = -3.4e38f, mx1 = -3.4e38f;
#pragma unroll
            for (int nf = 0; nf < 8; nf++) {
                mx0 = fmaxf(mx0, fmaxf(acc[mf][nf][0], acc[mf][nf][1]));
                mx1 = fmaxf(mx1, fmaxf(acc[mf][nf][2], acc[mf][nf][3]));
            }
            mx0 = fmaxf(mx0, __shfl_xor_sync(0xffffffffu, mx0, 1));
            mx0 = fmaxf(mx0, __shfl_xor_sync(0xffffffffu, mx0, 2));
            mx1 = fmaxf(mx1, __shfl_xor_sync(0xffffffffu, mx1, 1));
            mx1 = fmaxf(mx1, __shfl_xor_sync(0xffffffffu, mx1, 2));

            float s0 = 0.f, s1 = 0.f;
#pragma unroll
            for (int nf = 0; nf < 8; nf++) {
                s0 += __expf(acc[mf][nf][0] - mx0) + __expf(acc[mf][nf][1] - mx0);
                s1 += __expf(acc[mf][nf][2] - mx1) + __expf(acc[mf][nf][3] - mx1);
            }
            s0 += __shfl_xor_sync(0xffffffffu, s0, 1);
            s0 += __shfl_xor_sync(0xffffffffu, s0, 2);
            s1 += __shfl_xor_sync(0xffffffffu, s1, 1);
            s1 += __shfl_xor_sync(0xffffffffu, s1, 2);

            if (tig == 0) {
                size_t gr0 = ((size_t)bh * Ss + row0) * NPART + ntile * 4 + wn;
                pmax[gr0] = mx0; psum[gr0] = s0;
                size_t gr1 = gr0 + 8 * NPART;
                pmax[gr1] = mx1; psum[gr1] = s1;
            }

#pragma unroll
            for (int nf = 0; nf < 8; nf++)
                *(float2*)(arow + nf * 8) = make_float2(acc[mf][nf][0], acc[mf][nf][1]);
#pragma unroll
            for (int nf = 0; nf < 8; nf++)
                *(float2*)(arow8 + nf * 8) = make_float2(acc[mf][nf][2], acc[mf][nf][3]);
        }
    }
}

// ---------------------------------------------------------------------------
// Combine softmax partials: per row -> (max, 1/Z)
// ---------------------------------------------------------------------------
__global__ __launch_bounds__(256)
void combine_k(const float* __restrict__ pmax, const float* __restrict__ psum,
               float* __restrict__ rowm, float* __restrict__ rowz)
{
    int r = blockIdx.x * 256 + threadIdx.x;
    float m = -3.4e38f;
#pragma unroll
    for (int i = 0; i < NPART; i++) m = fmaxf(m, pmax[(size_t)r * NPART + i]);
    float z = 0.f;
#pragma unroll
    for (int i = 0; i < NPART; i++)
        z += psum[(size_t)r * NPART + i] * __expf(pmax[(size_t)r * NPART + i] - m);
    rowm[r] = m;
    rowz[r] = 1.f / z;
}

// ---------------------------------------------------------------------------
// Fused normalize + attn*V (known-good)
// ---------------------------------------------------------------------------
__global__ __launch_bounds__(256)
void attnv_k(float* __restrict__ attn, const float* __restrict__ Vt,
             const float* __restrict__ rowm, const float* __restrict__ rowz,
             float* __restrict__ O)
{
    __shared__ float As[2][8][128];
    __shared__ float Ws[2][8][64];

    int mt = blockIdx.x, bh = blockIdx.y;
    int m0 = mt * 128;
    float* Ab = attn + ((size_t)bh << 22) + (size_t)m0 * Ss;
    const float* Wb = Vt + (size_t)bh * DKk * Ss;

    int tid = threadIdx.x;
    int tx = tid & 15, ty = tid >> 4;
    int lr = tid >> 1;
    int lc = (tid & 1) * 4;

    float rm = rowm[bh * Ss + m0 + lr];
    float rz = rowz[bh * Ss + m0 + lr];

    float acc[8][4];
#pragma unroll
    for (int i = 0; i < 8; i++)
#pragma unroll
        for (int j = 0; j < 4; j++) acc[i][j] = 0.f;

    auto ldst = [&](int buf, int kt) {
        float4 v = *(const float4*)(Ab + (size_t)lr * Ss + kt + lc);
        float4 p;
        p.x = __expf(v.x - rm) * rz;
        p.y = __expf(v.y - rm) * rz;
        p.z = __expf(v.z - rm) * rz;
        p.w = __expf(v.w - rm) * rz;
        As[buf][lc + 0][lr] = p.x;
        As[buf][lc + 1][lr] = p.y;
        As[buf][lc + 2][lr] = p.z;
        As[buf][lc + 3][lr] = p.w;
        *(float4*)(Ab + (size_t)lr * Ss + kt + lc) = p;   // writeback normalized
        if (tid < 128) {
            float4 w = *(const float4*)(Wb + (size_t)lr * Ss + kt + lc);
            Ws[buf][lc + 0][lr] = w.x;
            Ws[buf][lc + 1][lr] = w.y;
            Ws[buf][lc + 2][lr] = w.z;
            Ws[buf][lc + 3][lr] = w.w;
        }
    };

    ldst(0, 0);
    __syncthreads();

    const int nk = Ss / 8;
    for (int t = 0; t < nk; t++) {
        int buf = t & 1;
        if (t + 1 < nk) ldst(buf ^ 1, (t + 1) * 8);
#pragma unroll
        for (int kk = 0; kk < 8; kk++) {
            float a[8], b[4];
            *(float4*)&a[0] = *(const float4*)&As[buf][kk][ty * 4];
            *(float4*)&a[4] = *(const float4*)&As[buf][kk][ty * 4 + 64];
            *(float4*)&b[0] = *(const float4*)&Ws[buf][kk][tx * 4];
#pragma unroll
            for (int i = 0; i < 8; i++)
#pragma unroll
                for (int j = 0; j < 4; j++)
                    acc[i][j] = fmaf(a[i], b[j], acc[i][j]);
        }
        __syncthreads();
    }

    size_t cbase = (size_t)(bh >> 4) * ((size_t)Ss * Dd) + (size_t)(bh & 15) * 64;
#pragma unroll
    for (int gi = 0; gi < 2; gi++) {
#pragma unroll
        for (int i = 0; i < 4; i++) {
            int m = m0 + ty * 4 + gi * 64 + i;
            int n = tx * 4;
            float4 v;
            v.x = acc[gi * 4 + i][0];
            v.y = acc[gi * 4 + i][1];
            v.z = acc[gi * 4 + i][2];
            v.w = acc[gi * 4 + i][3];
            *(float4*)(O + cbase + (size_t)m * Dd + n) = v;
        }
    }
}

// ---------------------------------------------------------------------------
extern "C" void kernel_launch(void* const* d_in, const int* in_sizes, int n_in,
                              void* d_out, int out_size)
{
    const float* x  = (const float*)d_in[0];
    const float* Wq = (const float*)d_in[1];
    const float* bq = (const float*)d_in[2];
    const float* Wk = (const float*)d_in[3];
    const float* bk = (const float*)d_in[4];
    const float* Wv = (const float*)d_in[5];
    const float* bv = (const float*)d_in[6];
    const float* Wo = (const float*)d_in[7];
    const float* bo = (const float*)d_in[8];
    const float* tw = (const float*)d_in[9];
    const float* fw = (const float*)d_in[10];

    float* out  = (float*)d_out;
    float* attn = out + (size_t)Mm * Dd;

    float *qaug, *kaug, *vt, *oo, *pmax, *psum, *rowm, *rowz;
    __half *qe, *ke;
    cudaGetSymbolAddress((void**)&qaug, g_Qaug);
    cudaGetSymbolAddress((void**)&kaug, g_Kaug);
    cudaGetSymbolAddress((void**)&qe,   g_Qe16);
    cudaGetSymbolAddress((void**)&ke,   g_Ke16);
    cudaGetSymbolAddress((void**)&vt,   g_Vt);
    cudaGetSymbolAddress((void**)&oo,   g_O);
    cudaGetSymbolAddress((void**)&pmax, g_pmax);
    cudaGetSymbolAddress((void**)&psum, g_psum);
    cudaGetSymbolAddress((void**)&rowm, g_rowm);
    cudaGetSymbolAddress((void**)&rowz, g_rowz);

    static const int SM16 = 2 * A16B + 2 * B16B;   // 61440
    cudaFuncSetAttribute(scores16_k<192, 12, 0>,
                         cudaFuncAttributeMaxDynamicSharedMemorySize, SM16);
    cudaFuncSetAttribute(scores16_k<0, 6, 1>,
                         cudaFuncAttributeMaxDynamicSharedMemorySize, SM16);

    dim3 blk(256);

    // twiddle first (so profiler's fixed capture index lands on a projection)
    twiddle_init_k<<<4, 256>>>();

    // projections
    sgemm_k<2, 1><<<dim3(8, 32, 1), blk>>>(x, 0, Wq, 0, bq, qaug, 0, 0, 1, Dd, Dd, Dd, 0);
    sgemm_k<2, 1><<<dim3(8, 32, 1), blk>>>(x, 0, Wk, 0, bk, kaug, 0, 0, 1, Dd, Dd, Dd, 0);
    sgemm_k<2, 2><<<dim3(8, 32, 1), blk>>>(x, 0, Wv, 0, bv, vt, 0, 0, 1, Dd, Dd, Dd, 0);

    // FFT
    fft_k<<<dim3(BHh, 2, 32), blk>>>(qaug, kaug, tw, fw);

    // fp16x2 split
    {
        int nblk = (int)(((size_t)BHh * Ss * 48) / 256);   // 12288
        convert16_k<1><<<nblk, 256>>>(qaug, qe);
        convert16_k<0><<<nblk, 256>>>(kaug, ke);
    }

    // freq scores (half rows + conjugate mirror), staged raw into attn region
    scores16_k<192, 12, 0><<<dim3(8, 9, BHh), blk, SM16>>>(qe, ke, attn, pmax, psum);

    // time scores + freq add + softmax partials
    scores16_k<0, 6, 1><<<dim3(8, 16, BHh), blk, SM16>>>(qe, ke, attn, pmax, psum);

    // combine partials -> per-row (max, 1/Z)
    combine_k<<<(BHh * Ss) / 256, 256>>>(pmax, psum, rowm, rowz);

    // fused normalize + attn*V
    attnv_k<<<dim3(16, BHh), blk>>>(attn, vt, rowm, rowz, oo);

    // out projection
    sgemm_k<2, 0><<<dim3(8, 32, 1), blk>>>(oo, 0, Wo, 0, bo, out, 0, 0, 1, Dd, Dd, Dd, Dd);
}

// round 7
// speedup vs baseline: 1.2448x; 1.2448x over previous
#include <cuda_runtime.h>
#include <cuda_fp16.h>
#include <math.h>
#include <stdint.h>

// Problem constants
#define Bb   2
#define Ss   2048
#define Dd   1024
#define Hh   16
#define DKk  64
#define AUGC 192              // [time(64) | Re(64) | Im(64)]
#define ECOLS 576             // fp16 ext: [time 3x64 | freq 3x128]
#define BHh  (Bb * Hh)        // 32
#define Mm   (Bb * Ss)        // 4096
#define NPART 32              // softmax partials per row: 8 ntiles x 4 wn-warps

// Scratch
__device__ float   g_Qaug[(size_t)BHh * Ss * AUGC];
__device__ float   g_Kaug[(size_t)BHh * Ss * AUGC];
__device__ __half  g_Qe16[(size_t)BHh * Ss * ECOLS];
__device__ __half  g_Ke16[(size_t)BHh * Ss * ECOLS];
__device__ __half  g_V16 [(size_t)BHh * DKk * 2 * Ss];   // [bh][dk][part h/l][s]
__device__ float   g_Freq[(size_t)BHh * 1025 * Ss];      // staged freq rows 0..1024
__device__ float   g_O   [(size_t)Mm * Dd];
__device__ float   g_pmax[(size_t)BHh * Ss * NPART];
__device__ float   g_psum[(size_t)BHh * Ss * NPART];
__device__ float   g_rowm[(size_t)BHh * Ss];
__device__ float   g_rowz[(size_t)BHh * Ss];
__device__ float2  g_twid[1024];

// ---------------------------------------------------------------------------
// Twiddle init (fp64-accurate)
// ---------------------------------------------------------------------------
__global__ void twiddle_init_k() {
    int t = blockIdx.x * blockDim.x + threadIdx.x;
    if (t < 1024) {
        double ang = -2.0 * 3.14159265358979323846 * (double)t / 2048.0;
        double s, c;
        sincos(ang, &s, &c);
        g_twid[t] = make_float2((float)c, (float)s);
    }
}

// ---------------------------------------------------------------------------
// Generic fp32 SGEMM: C = A * W^T (+bias)
// MODE 0: plain; MODE 1: aug scatter; MODE 2: fp16-split V^T scatter
// ---------------------------------------------------------------------------
template<int NG, int MODE>
__global__ __launch_bounds__(256)
void sgemm_k(const float* __restrict__ A, size_t saZ,
             const float* __restrict__ W, size_t swZ,
             const float* __restrict__ bias,
             float* __restrict__ C, size_t scB1, size_t scB2, int Hdiv,
             int K, int lda, int ldw, int ldc)
{
    const int BM = 128, BK = 8;
    const int BN = 64 * NG;
    __shared__ float As[2][BK][BM];
    __shared__ float Ws[2][BK][BN];

    int z = blockIdx.z;
    const float* Ab = A + (size_t)z * saZ;
    const float* Wb = W + (size_t)z * swZ;
    size_t cbase = (size_t)(z / Hdiv) * scB1 + (size_t)(z % Hdiv) * scB2;

    int m0 = blockIdx.y * BM;
    int n0 = blockIdx.x * BN;
    int tid = threadIdx.x;
    int tx = tid & 15, ty = tid >> 4;
    int lr = tid >> 1;
    int lc = (tid & 1) * 4;

    float acc[8][4 * NG];
#pragma unroll
    for (int i = 0; i < 8; i++)
#pragma unroll
        for (int j = 0; j < 4 * NG; j++) acc[i][j] = 0.f;

    auto ldst = [&](int buf, int kt) {
        float4 av = *(const float4*)(Ab + (size_t)(m0 + lr) * lda + kt + lc);
        As[buf][lc + 0][lr] = av.x;
        As[buf][lc + 1][lr] = av.y;
        As[buf][lc + 2][lr] = av.z;
        As[buf][lc + 3][lr] = av.w;
        if (NG == 2 || tid < 128) {
            float4 wv = *(const float4*)(Wb + (size_t)(n0 + lr) * ldw + kt + lc);
            Ws[buf][lc + 0][lr] = wv.x;
            Ws[buf][lc + 1][lr] = wv.y;
            Ws[buf][lc + 2][lr] = wv.z;
            Ws[buf][lc + 3][lr] = wv.w;
        }
    };

    ldst(0, 0);
    __syncthreads();

    int nk = K / BK;
    for (int t = 0; t < nk; t++) {
        int buf = t & 1;
        if (t + 1 < nk) ldst(buf ^ 1, (t + 1) * BK);
#pragma unroll
        for (int kk = 0; kk < BK; kk++) {
            float a[8], b[4 * NG];
            *(float4*)&a[0] = *(const float4*)&As[buf][kk][ty * 4];
            *(float4*)&a[4] = *(const float4*)&As[buf][kk][ty * 4 + 64];
            *(float4*)&b[0] = *(const float4*)&Ws[buf][kk][tx * 4];
            if (NG == 2)
                *(float4*)&b[4] = *(const float4*)&Ws[buf][kk][tx * 4 + 64];
#pragma unroll
            for (int i = 0; i < 8; i++)
#pragma unroll
                for (int j = 0; j < 4 * NG; j++)
                    acc[i][j] = fmaf(a[i], b[j], acc[i][j]);
        }
        __syncthreads();
    }

#pragma unroll
    for (int gi = 0; gi < 2; gi++) {
#pragma unroll
        for (int i = 0; i < 4; i++) {
            int m = m0 + ty * 4 + gi * 64 + i;
#pragma unroll
            for (int gj = 0; gj < NG; gj++) {
                int n = n0 + tx * 4 + gj * 64;
                float4 v;
                v.x = acc[gi * 4 + i][gj * 4 + 0];
                v.y = acc[gi * 4 + i][gj * 4 + 1];
                v.z = acc[gi * 4 + i][gj * 4 + 2];
                v.w = acc[gi * 4 + i][gj * 4 + 3];
                if (bias) {
                    v.x += bias[n + 0]; v.y += bias[n + 1];
                    v.z += bias[n + 2]; v.w += bias[n + 3];
                }
                if (MODE == 0) {
                    *(float4*)(C + cbase + (size_t)m * ldc + n) = v;
                } else if (MODE == 1) {
                    int bb = m >> 11, s = m & 2047;
                    int hh = n >> 6,  d = n & 63;
                    *(float4*)(C + ((size_t)((bb * 16 + hh) * 2048 + s)) * AUGC + d) = v;
                } else {
                    // fp16 split V^T: [bh][dk][part][s]
                    int bb = m >> 11, s = m & 2047;
                    int hh = n >> 6,  d = n & 63;
                    __half* vp = (__half*)C
                        + (((size_t)(bb * 16 + hh) * 64 + d) * 2) * 2048 + s;
                    float vals[4] = {v.x, v.y, v.z, v.w};
#pragma unroll
                    for (int q = 0; q < 4; q++) {
                        __half h = __float2half_rn(vals[q]);
                        __half l = __float2half_rn(vals[q] - __half2float(h));
                        vp[(size_t)(q * 2) * 2048]     = h;
                        vp[(size_t)(q * 2 + 1) * 2048] = l;
                    }
                }
            }
        }
    }
}

// ---------------------------------------------------------------------------
// FFT (known-good)
// ---------------------------------------------------------------------------
__global__ __launch_bounds__(256)
void fft_k(float* qaug, float* kaug, const float* twp, const float* fwp)
{
    __shared__ float  sr[2][2048];
    __shared__ float  si[2][2048];
    __shared__ float2 tw[1024];

    int bh     = blockIdx.x;
    int tensor = blockIdx.y;
    int dk0    = blockIdx.z * 2;
    float* base = (tensor == 0 ? qaug : kaug) + (size_t)bh * Ss * AUGC;
    int tid = threadIdx.x;

    for (int t = tid; t < 1024; t += 256) tw[t] = g_twid[t];

    for (int idx = tid; idx < 2 * Ss; idx += 256) {
        int l = idx & 1;
        int s = idx >> 1;
        float v = base[(size_t)s * AUGC + dk0 + l];
        int rs = __brev((unsigned)s) >> 21;
        sr[l][rs] = v;
        si[l][rs] = 0.f;
    }
    __syncthreads();

    for (int len = 2; len <= 2048; len <<= 1) {
        int half = len >> 1;
        int step = 2048 / len;
        for (int idx = tid; idx < 2048; idx += 256) {
            int l   = idx >> 10;
            int bix = idx & 1023;
            int grp = bix / half;
            int pos = bix - grp * half;
            int i0 = grp * len + pos;
            int i1 = i0 + half;
            float2 w = tw[pos * step];
            float xr = sr[l][i1], xi = si[l][i1];
            float tr = xr * w.x - xi * w.y;
            float ti = xr * w.y + xi * w.x;
            float ur = sr[l][i0], ui = si[l][i0];
            sr[l][i0] = ur + tr;  si[l][i0] = ui + ti;
            sr[l][i1] = ur - tr;  si[l][i1] = ui - ti;
        }
        __syncthreads();
    }

    float ft, ff;
    if (tensor == 0) { ft = twp[0] * 0.125f; ff = fwp[0] * 0.125f; }
    else             { ft = 1.f;             ff = 1.f; }

    for (int idx = tid; idx < 2 * Ss; idx += 256) {
        int l = idx & 1;
        int s = idx >> 1;
        size_t o = (size_t)s * AUGC + dk0 + l;
        if (tensor == 0) base[o] *= ft;
        base[o + 64]  = sr[l][s] * ff;
        base[o + 128] = si[l][s] * ff;
    }
}

// ---------------------------------------------------------------------------
// Convert aug (192 f32) -> fp16x2 ext (576 fp16)
// ---------------------------------------------------------------------------
__device__ __forceinline__ uint32_t packh2(__half a, __half b) {
    __half2 p = __halves2half2(a, b);
    return *reinterpret_cast<uint32_t*>(&p);
}
template<int QMODE>
__global__ __launch_bounds__(256)
void convert16_k(const float* __restrict__ src, __half* __restrict__ dst)
{
    size_t i4 = (size_t)blockIdx.x * 256 + threadIdx.x;
    size_t row = i4 / 48;
    int c4 = (int)(i4 % 48);
    float4 x = ((const float4*)src)[i4];

    __half hx = __float2half_rn(x.x), hy = __float2half_rn(x.y);
    __half hz = __float2half_rn(x.z), hw = __float2half_rn(x.w);
    __half lx = __float2half_rn(x.x - __half2float(hx));
    __half ly = __float2half_rn(x.y - __half2float(hy));
    __half lz = __float2half_rn(x.z - __half2float(hz));
    __half lw = __float2half_rn(x.w - __half2float(hw));

    uint2 H, L;
    H.x = packh2(hx, hy); H.y = packh2(hz, hw);
    L.x = packh2(lx, ly); L.y = packh2(lz, lw);

    __half* drow = dst + row * ECOLS;
    int base, f, span;
    if (c4 < 16) { base = 0;   f = c4 * 4;      span = 64;  }
    else         { base = 192; f = c4 * 4 - 64; span = 128; }

    *(uint2*)(drow + base + f) = H;
    if (QMODE) {
        *(uint2*)(drow + base + span + f)     = L;
        *(uint2*)(drow + base + 2 * span + f) = H;
    } else {
        *(uint2*)(drow + base + span + f)     = H;
        *(uint2*)(drow + base + 2 * span + f) = L;
    }
}

// ---------------------------------------------------------------------------
// fp16 mma scores. EPI=0 (freq): writes rows<=1024 coalesced into Freq.
// EPI=1 (time): adds Freq (direct or conjugate-mirrored), stores combined
// logits + per-(row,ntile,wn) softmax partials.
// ---------------------------------------------------------------------------
#define A16B (128 * 80)
#define B16B (256 * 80)

__device__ __forceinline__ void mma_fp16(float c[4], const uint32_t a[4],
                                         const uint32_t b[2]) {
    asm volatile(
        "mma.sync.aligned.m16n8k16.row.col.f32.f16.f16.f32 "
        "{%0,%1,%2,%3}, {%4,%5,%6,%7}, {%8,%9}, {%0,%1,%2,%3};"
        : "+f"(c[0]), "+f"(c[1]), "+f"(c[2]), "+f"(c[3])
        : "r"(a[0]), "r"(a[1]), "r"(a[2]), "r"(a[3]), "r"(b[0]), "r"(b[1]));
}

template<int KOFF, int NCH, int EPI>
__global__ __launch_bounds__(256, 1)
void scores16_k(const __half* __restrict__ Qe, const __half* __restrict__ Ke,
                float* __restrict__ attn, float* __restrict__ Freq,
                float* __restrict__ pmax, float* __restrict__ psum)
{
    extern __shared__ char smc[];

    const int tid  = threadIdx.x;
    const int wid  = tid >> 5;
    const int lane = tid & 31;
    const int g    = lane >> 2;
    const int tig  = lane & 3;
    const int wm   = wid >> 2;
    const int wn   = wid & 3;

    const int ntile = blockIdx.x;
    const int mtile = blockIdx.y;
    const int bh    = blockIdx.z;
    const int m0 = mtile * 128;
    const int n0 = ntile * 256;

    const __half* Ag = Qe + ((size_t)bh * Ss + m0) * ECOLS + KOFF;
    const __half* Bg = Ke + ((size_t)bh * Ss + n0) * ECOLS + KOFF;

    const int lrow = tid >> 3;
    const int t8   = tid & 7;

    float acc[4][8][4];
#pragma unroll
    for (int mf = 0; mf < 4; mf++)
#pragma unroll
        for (int nf = 0; nf < 8; nf++)
#pragma unroll
            for (int j = 0; j < 4; j++) acc[mf][nf][j] = 0.f;

    uint2 ra[4], rb[8];
    auto ldg = [&](int c) {
#pragma unroll
        for (int i = 0; i < 4; i++)
            ra[i] = *(const uint2*)(Ag + (size_t)(lrow + i * 32) * ECOLS + c * 32 + t8 * 4);
#pragma unroll
        for (int i = 0; i < 8; i++)
            rb[i] = *(const uint2*)(Bg + (size_t)(lrow + i * 32) * ECOLS + c * 32 + t8 * 4);
    };
    auto sts = [&](int b) {
        char* a16 = smc + b * A16B;
#pragma unroll
        for (int i = 0; i < 4; i++)
            *(uint2*)(a16 + (lrow + i * 32) * 80 + t8 * 8) = ra[i];
        char* b16 = smc + 2 * A16B + b * B16B;
#pragma unroll
        for (int i = 0; i < 8; i++)
            *(uint2*)(b16 + (lrow + i * 32) * 80 + t8 * 8) = rb[i];
    };

    ldg(0);
    sts(0);
    __syncthreads();

    for (int c = 0; c < NCH; c++) {
        int buf = c & 1;
        if (c + 1 < NCH) ldg(c + 1);

        const char* a16 = smc + buf * A16B + (wm * 64) * 80;
        const char* b16 = smc + 2 * A16B + buf * B16B + (wn * 64) * 80;
#pragma unroll
        for (int st = 0; st < 2; st++) {
            int kb = st * 32;
            uint32_t bfr[8][2];
#pragma unroll
            for (int nf = 0; nf < 8; nf++) {
                const char* br = b16 + (nf * 8 + g) * 80 + kb + tig * 4;
                bfr[nf][0] = *(const uint32_t*)br;
                bfr[nf][1] = *(const uint32_t*)(br + 16);
            }
#pragma unroll
            for (int mf = 0; mf < 4; mf++) {
                const char* ar = a16 + (mf * 16 + g) * 80 + kb + tig * 4;
                uint32_t afr[4];
                afr[0] = *(const uint32_t*)ar;
                afr[1] = *(const uint32_t*)(ar + 8 * 80);
                afr[2] = *(const uint32_t*)(ar + 16);
                afr[3] = *(const uint32_t*)(ar + 8 * 80 + 16);
#pragma unroll
                for (int nf = 0; nf < 8; nf++)
                    mma_fp16(acc[mf][nf], afr, bfr[nf]);
            }
        }
        if (c + 1 < NCH) sts(buf ^ 1);
        __syncthreads();
    }

    const int cbase = n0 + wn * 64 + tig * 2;

    if (EPI == 0) {
        // freq pass: stage rows <= 1024 coalesced (no mirror scatter)
#pragma unroll
        for (int mf = 0; mf < 4; mf++) {
            int r0 = m0 + wm * 64 + mf * 16 + g;
#pragma unroll
            for (int hf = 0; hf < 2; hf++) {
                int r = r0 + hf * 8;
                if (r <= 1024) {
                    float* frow = Freq + ((size_t)bh * 1025 + r) * Ss;
#pragma unroll
                    for (int nf = 0; nf < 8; nf++)
                        *(float2*)(frow + cbase + nf * 8) =
                            make_float2(acc[mf][nf][hf * 2], acc[mf][nf][hf * 2 + 1]);
                }
            }
        }
    } else {
        // time pass: add staged freq (direct or mirrored), store combined
#pragma unroll
        for (int mf = 0; mf < 4; mf++) {
            int row0 = m0 + wm * 64 + mf * 16 + g;
#pragma unroll
            for (int hf = 0; hf < 2; hf++) {
                int r = row0 + hf * 8;
                if (r <= 1024) {
                    const float* fr = Freq + ((size_t)bh * 1025 + r) * Ss;
#pragma unroll
                    for (int nf = 0; nf < 8; nf++) {
                        float2 f = *(const float2*)(fr + cbase + nf * 8);
                        acc[mf][nf][hf * 2]     += f.x;
                        acc[mf][nf][hf * 2 + 1] += f.y;
                    }
                } else {
                    const float* fr = Freq + ((size_t)bh * 1025 + (2048 - r)) * Ss;
#pragma unroll
                    for (int nf = 0; nf < 8; nf++) {
                        int c0 = cbase + nf * 8;
                        acc[mf][nf][hf * 2]     += fr[(2048 - c0) & 2047];
                        acc[mf][nf][hf * 2 + 1] += fr[2047 - c0];
                    }
                }
            }

            float mx0 = -3.4e38f, mx1 = -3.4e38f;
#pragma unroll
            for (int nf = 0; nf < 8; nf++) {
                mx0 = fmaxf(mx0, fmaxf(acc[mf][nf][0], acc[mf][nf][1]));
                mx1 = fmaxf(mx1, fmaxf(acc[mf][nf][2], acc[mf][nf][3]));
            }
            mx0 = fmaxf(mx0, __shfl_xor_sync(0xffffffffu, mx0, 1));
            mx0 = fmaxf(mx0, __shfl_xor_sync(0xffffffffu, mx0, 2));
            mx1 = fmaxf(mx1, __shfl_xor_sync(0xffffffffu, mx1, 1));
            mx1 = fmaxf(mx1, __shfl_xor_sync(0xffffffffu, mx1, 2));

            float s0 = 0.f, s1 = 0.f;
#pragma unroll
            for (int nf = 0; nf < 8; nf++) {
                s0 += __expf(acc[mf][nf][0] - mx0) + __expf(acc[mf][nf][1] - mx0);
                s1 += __expf(acc[mf][nf][2] - mx1) + __expf(acc[mf][nf][3] - mx1);
            }
            s0 += __shfl_xor_sync(0xffffffffu, s0, 1);
            s0 += __shfl_xor_sync(0xffffffffu, s0, 2);
            s1 += __shfl_xor_sync(0xffffffffu, s1, 1);
            s1 += __shfl_xor_sync(0xffffffffu, s1, 2);

            if (tig == 0) {
                size_t gr0 = ((size_t)bh * Ss + row0) * NPART + ntile * 4 + wn;
                pmax[gr0] = mx0; psum[gr0] = s0;
                size_t gr1 = gr0 + 8 * NPART;
                pmax[gr1] = mx1; psum[gr1] = s1;
            }

            float* arow  = attn + ((size_t)bh << 22) + (size_t)row0 * Ss + cbase;
            float* arow8 = arow + 8 * Ss;
#pragma unroll
            for (int nf = 0; nf < 8; nf++)
                *(float2*)(arow + nf * 8) = make_float2(acc[mf][nf][0], acc[mf][nf][1]);
#pragma unroll
            for (int nf = 0; nf < 8; nf++)
                *(float2*)(arow8 + nf * 8) = make_float2(acc[mf][nf][2], acc[mf][nf][3]);
        }
    }
}

// ---------------------------------------------------------------------------
// Combine softmax partials: per row -> (max, 1/Z)
// ---------------------------------------------------------------------------
__global__ __launch_bounds__(256)
void combine_k(const float* __restrict__ pmax, const float* __restrict__ psum,
               float* __restrict__ rowm, float* __restrict__ rowz)
{
    int r = blockIdx.x * 256 + threadIdx.x;
    float m = -3.4e38f;
#pragma unroll
    for (int i = 0; i < NPART; i++) m = fmaxf(m, pmax[(size_t)r * NPART + i]);
    float z = 0.f;
#pragma unroll
    for (int i = 0; i < NPART; i++)
        z += psum[(size_t)r * NPART + i] * __expf(pmax[(size_t)r * NPART + i] - m);
    rowm[r] = m;
    rowz[r] = 1.f / z;
}

// ---------------------------------------------------------------------------
// Fused normalize + attn*V on fp16 mma.
// A chunk = [p16 | p16] (fp16), B chunk = [vh16 | vl16]; same accumulator.
// CTA tile M=128, N=64, 128 chunks of 16 real k. Writes normalized attn (fp32).
// grid = (16 mtiles, 32 bh), 256 threads.
// ---------------------------------------------------------------------------
#define AVA (128 * 80)
#define AVB (64 * 80)

__global__ __launch_bounds__(256, 1)
void attnv16_k(float* __restrict__ attn, const __half* __restrict__ V16,
               const float* __restrict__ rowm, const float* __restrict__ rowz,
               float* __restrict__ O)
{
    __shared__ char smc[2 * AVA + 2 * AVB];

    const int tid  = threadIdx.x;
    const int wid  = tid >> 5;
    const int lane = tid & 31;
    const int g    = lane >> 2;
    const int tig  = lane & 3;
    const int wm   = wid & 3;        // 4 m-strips of 32
    const int wn   = wid >> 2;       // 2 n-strips of 32

    const int mt = blockIdx.x, bh = blockIdx.y;
    const int m0 = mt * 128;
    float* Ab = attn + ((size_t)bh << 22) + (size_t)m0 * Ss;
    const __half* Vb = V16 + (size_t)bh * 128 * 2048;

    // prologue mapping: 2 rows per thread (prow, prow+64), 4 k-floats each
    const int prow = tid >> 2;       // 0..63
    const int pf4  = tid & 3;
    const float rm0 = rowm[bh * Ss + m0 + prow];
    const float rz0 = rowz[bh * Ss + m0 + prow];
    const float rm1 = rowm[bh * Ss + m0 + prow + 64];
    const float rz1 = rowz[bh * Ss + m0 + prow + 64];

    // B mapping: seg = (n, part), 8 halfs each
    const int bseg  = tid >> 1;      // 0..127
    const int bn    = bseg & 63;
    const int bpart = bseg >> 6;
    const int bh16  = tid & 1;

    float acc[2][4][4];
#pragma unroll
    for (int mf = 0; mf < 2; mf++)
#pragma unroll
        for (int nf = 0; nf < 4; nf++)
#pragma unroll
            for (int j = 0; j < 4; j++) acc[mf][nf][j] = 0.f;

    float4 pa[2];
    uint4  vb;

    auto ldg = [&](int c) {
        pa[0] = *(const float4*)(Ab + (size_t)prow * Ss + c * 16 + pf4 * 4);
        pa[1] = *(const float4*)(Ab + (size_t)(prow + 64) * Ss + c * 16 + pf4 * 4);
        vb = *(const uint4*)(Vb + ((size_t)bn * 2 + bpart) * 2048 + c * 16 + bh16 * 8);
    };
    auto sts = [&](int b, int c) {
        char* a16 = smc + b * AVA;
#pragma unroll
        for (int i = 0; i < 2; i++) {
            float rm = i ? rm1 : rm0, rz = i ? rz1 : rz0;
            float4 p;
            p.x = __expf(pa[i].x - rm) * rz;
            p.y = __expf(pa[i].y - rm) * rz;
            p.z = __expf(pa[i].z - rm) * rz;
            p.w = __expf(pa[i].w - rm) * rz;
            // writeback normalized attn (fp32, exact output)
            *(float4*)(Ab + (size_t)(prow + i * 64) * Ss + c * 16 + pf4 * 4) = p;
            uint2 hp;
            hp.x = packh2(__float2half_rn(p.x), __float2half_rn(p.y));
            hp.y = packh2(__float2half_rn(p.z), __float2half_rn(p.w));
            char* arow = a16 + (prow + i * 64) * 80;
            *(uint2*)(arow + pf4 * 8)      = hp;   // k-slots 0..15
            *(uint2*)(arow + 32 + pf4 * 8) = hp;   // duplicated k-slots 16..31
        }
        char* b16 = smc + 2 * AVA + b * AVB;
        *(uint4*)(b16 + bn * 80 + bpart * 32 + bh16 * 16) = vb;
    };

    ldg(0);
    sts(0, 0);
    __syncthreads();

    const int NCH = 128;
    for (int c = 0; c < NCH; c++) {
        int buf = c & 1;
        if (c + 1 < NCH) ldg(c + 1);

        const char* a16 = smc + buf * AVA + (wm * 32) * 80;
        const char* b16 = smc + 2 * AVA + buf * AVB + (wn * 32) * 80;
#pragma unroll
        for (int st = 0; st < 2; st++) {
            int kb = st * 32;
            uint32_t bfr[4][2];
#pragma unroll
            for (int nf = 0; nf < 4; nf++) {
                const char* br = b16 + (nf * 8 + g) * 80 + kb + tig * 4;
                bfr[nf][0] = *(const uint32_t*)br;
                bfr[nf][1] = *(const uint32_t*)(br + 16);
            }
#pragma unroll
            for (int mf = 0; mf < 2; mf++) {
                const char* ar = a16 + (mf * 16 + g) * 80 + kb + tig * 4;
                uint32_t afr[4];
                afr[0] = *(const uint32_t*)ar;
                afr[1] = *(const uint32_t*)(ar + 8 * 80);
                afr[2] = *(const uint32_t*)(ar + 16);
                afr[3] = *(const uint32_t*)(ar + 8 * 80 + 16);
#pragma unroll
                for (int nf = 0; nf < 4; nf++)
                    mma_fp16(acc[mf][nf], afr, bfr[nf]);
            }
        }
        if (c + 1 < NCH) sts(buf ^ 1, c + 1);
        __syncthreads();
    }

    // epilogue: O[b*s][h*64+dk]
    size_t cb = (size_t)(bh >> 4) * ((size_t)Ss * Dd) + (size_t)(bh & 15) * 64;
#pragma unroll
    for (int mf = 0; mf < 2; mf++) {
        int row0 = m0 + wm * 32 + mf * 16 + g;
#pragma unroll
        for (int nf = 0; nf < 4; nf++) {
            int n = wn * 32 + nf * 8 + tig * 2;
            *(float2*)(O + cb + (size_t)row0 * Dd + n) =
                make_float2(acc[mf][nf][0], acc[mf][nf][1]);
            *(float2*)(O + cb + (size_t)(row0 + 8) * Dd + n) =
                make_float2(acc[mf][nf][2], acc[mf][nf][3]);
        }
    }
}

// ---------------------------------------------------------------------------
extern "C" void kernel_launch(void* const* d_in, const int* in_sizes, int n_in,
                              void* d_out, int out_size)
{
    const float* x  = (const float*)d_in[0];
    const float* Wq = (const float*)d_in[1];
    const float* bq = (const float*)d_in[2];
    const float* Wk = (const float*)d_in[3];
    const float* bk = (const float*)d_in[4];
    const float* Wv = (const float*)d_in[5];
    const float* bv = (const float*)d_in[6];
    const float* Wo = (const float*)d_in[7];
    const float* bo = (const float*)d_in[8];
    const float* tw = (const float*)d_in[9];
    const float* fw = (const float*)d_in[10];

    float* out  = (float*)d_out;
    float* attn = out + (size_t)Mm * Dd;

    float *qaug, *kaug, *freq, *oo, *pmax, *psum, *rowm, *rowz;
    __half *qe, *ke, *v16;
    cudaGetSymbolAddress((void**)&qaug, g_Qaug);
    cudaGetSymbolAddress((void**)&kaug, g_Kaug);
    cudaGetSymbolAddress((void**)&qe,   g_Qe16);
    cudaGetSymbolAddress((void**)&ke,   g_Ke16);
    cudaGetSymbolAddress((void**)&v16,  g_V16);
    cudaGetSymbolAddress((void**)&freq, g_Freq);
    cudaGetSymbolAddress((void**)&oo,   g_O);
    cudaGetSymbolAddress((void**)&pmax, g_pmax);
    cudaGetSymbolAddress((void**)&psum, g_psum);
    cudaGetSymbolAddress((void**)&rowm, g_rowm);
    cudaGetSymbolAddress((void**)&rowz, g_rowz);

    static const int SM16 = 2 * A16B + 2 * B16B;   // 61440
    cudaFuncSetAttribute(scores16_k<192, 12, 0>,
                         cudaFuncAttributeMaxDynamicSharedMemorySize, SM16);
    cudaFuncSetAttribute(scores16_k<0, 6, 1>,
                         cudaFuncAttributeMaxDynamicSharedMemorySize, SM16);

    dim3 blk(256);

    twiddle_init_k<<<4, 256>>>();

    // projections (V writes fp16 split directly)
    sgemm_k<2, 1><<<dim3(8, 32, 1), blk>>>(x, 0, Wq, 0, bq, qaug, 0, 0, 1, Dd, Dd, Dd, 0);
    sgemm_k<2, 1><<<dim3(8, 32, 1), blk>>>(x, 0, Wk, 0, bk, kaug, 0, 0, 1, Dd, Dd, Dd, 0);
    sgemm_k<2, 2><<<dim3(8, 32, 1), blk>>>(x, 0, Wv, 0, bv, (float*)v16, 0, 0, 1, Dd, Dd, Dd, 0);

    // FFT
    fft_k<<<dim3(BHh, 2, 32), blk>>>(qaug, kaug, tw, fw);

    // fp16x2 split
    {
        int nblk = (int)(((size_t)BHh * Ss * 48) / 256);   // 12288
        convert16_k<1><<<nblk, 256>>>(qaug, qe);
        convert16_k<0><<<nblk, 256>>>(kaug, ke);
    }

    // freq scores rows 0..1024 -> staged (coalesced)
    scores16_k<192, 12, 0><<<dim3(8, 9, BHh), blk, SM16>>>(qe, ke, attn, freq, pmax, psum);

    // time scores + freq add (direct/mirror) + softmax partials
    scores16_k<0, 6, 1><<<dim3(8, 16, BHh), blk, SM16>>>(qe, ke, attn, freq, pmax, psum);

    // combine partials -> per-row (max, 1/Z)
    combine_k<<<(BHh * Ss) / 256, 256>>>(pmax, psum, rowm, rowz);

    // fused normalize + attn*V on fp16 mma
    attnv16_k<<<dim3(16, BHh), blk>>>(attn, v16, rowm, rowz, oo);

    // out projection
    sgemm_k<2, 0><<<dim3(8, 32, 1), blk>>>(oo, 0, Wo, 0, bo, out, 0, 0, 1, Dd, Dd, Dd, Dd);
}

// round 8
// speedup vs baseline: 1.5924x; 1.2792x over previous
#include <cuda_runtime.h>
#include <cuda_fp16.h>
#include <math.h>
#include <stdint.h>

// Problem constants
#define Bb   2
#define Ss   2048
#define Dd   1024
#define Hh   16
#define DKk  64
#define AUGC 192              // [time(64) | Re(64) | Im(64)]
#define ECOLS 576             // fp16 ext: [time 3x64 | freq 3x128]
#define XEXT 3072             // fp16 3-term ext for D=1024 GEMMs
#define BHh  (Bb * Hh)        // 32
#define Mm   (Bb * Ss)        // 4096
#define NPART 32

// Scratch
__device__ float   g_Qaug[(size_t)BHh * Ss * AUGC];
__device__ float   g_Kaug[(size_t)BHh * Ss * AUGC];
__device__ __half  g_Qe16[(size_t)BHh * Ss * ECOLS];
__device__ __half  g_Ke16[(size_t)BHh * Ss * ECOLS];
__device__ __half  g_V16 [(size_t)BHh * DKk * 2 * Ss];   // [bh][dk][part h/l][s]
__device__ float   g_Freq[(size_t)BHh * 1025 * Ss];      // staged freq rows 0..1024
__device__ __half  g_Xext[(size_t)Mm * XEXT];            // [xh|xl|xh]
__device__ __half  g_Wq16[(size_t)Dd * XEXT];            // [Wh|Wh|Wl]
__device__ __half  g_Wk16[(size_t)Dd * XEXT];
__device__ __half  g_Wv16[(size_t)Dd * XEXT];
__device__ __half  g_Wo16[(size_t)Dd * XEXT];
__device__ __half  g_Oext[(size_t)Mm * XEXT];            // [oh|ol|oh]
__device__ float   g_pmax[(size_t)BHh * Ss * NPART];
__device__ float   g_psum[(size_t)BHh * Ss * NPART];
__device__ float   g_rowm[(size_t)BHh * Ss];
__device__ float   g_rowz[(size_t)BHh * Ss];
__device__ float2  g_twid[1024];

// ---------------------------------------------------------------------------
__device__ __forceinline__ uint32_t packh2(__half a, __half b) {
    __half2 p = __halves2half2(a, b);
    return *reinterpret_cast<uint32_t*>(&p);
}
__device__ __forceinline__ void mma_fp16(float c[4], const uint32_t a[4],
                                         const uint32_t b[2]) {
    asm volatile(
        "mma.sync.aligned.m16n8k16.row.col.f32.f16.f16.f32 "
        "{%0,%1,%2,%3}, {%4,%5,%6,%7}, {%8,%9}, {%0,%1,%2,%3};"
        : "+f"(c[0]), "+f"(c[1]), "+f"(c[2]), "+f"(c[3])
        : "r"(a[0]), "r"(a[1]), "r"(a[2]), "r"(a[3]), "r"(b[0]), "r"(b[1]));
}

// ---------------------------------------------------------------------------
// Twiddle init (fp64-accurate)
// ---------------------------------------------------------------------------
__global__ void twiddle_init_k() {
    int t = blockIdx.x * blockDim.x + threadIdx.x;
    if (t < 1024) {
        double ang = -2.0 * 3.14159265358979323846 * (double)t / 2048.0;
        double s, c;
        sincos(ang, &s, &c);
        g_twid[t] = make_float2((float)c, (float)s);
    }
}

// ---------------------------------------------------------------------------
// Converters: f32 -> fp16 3-term ext
//   WMODE=0 (activation A-side): [h | l | h]
//   WMODE=1 (weight B-side):     [h | h | l]
// One float4 per thread; SPAN = row length in f32 (1024).
// ---------------------------------------------------------------------------
template<int WMODE>
__global__ __launch_bounds__(256)
void convext_k(const float* __restrict__ src, __half* __restrict__ dst)
{
    size_t i4 = (size_t)blockIdx.x * 256 + threadIdx.x;   // 256 float4 per row
    size_t row = i4 >> 8;
    int c = (int)(i4 & 255) * 4;
    float4 x = ((const float4*)src)[i4];

    __half hx = __float2half_rn(x.x), hy = __float2half_rn(x.y);
    __half hz = __float2half_rn(x.z), hw = __float2half_rn(x.w);
    uint2 H, L;
    H.x = packh2(hx, hy); H.y = packh2(hz, hw);
    L.x = packh2(__float2half_rn(x.x - __half2float(hx)),
                 __float2half_rn(x.y - __half2float(hy)));
    L.y = packh2(__float2half_rn(x.z - __half2float(hz)),
                 __float2half_rn(x.w - __half2float(hw)));

    __half* d = dst + row * XEXT;
    *(uint2*)(d + c) = H;
    if (WMODE == 0) {
        *(uint2*)(d + 1024 + c) = L;
        *(uint2*)(d + 2048 + c) = H;
    } else {
        *(uint2*)(d + 1024 + c) = H;
        *(uint2*)(d + 2048 + c) = L;
    }
}

// ---------------------------------------------------------------------------
// fp16 3-term GEMM: C = Aext * Bext^T + bias.  K=3072 fp16 (96 chunks of 32).
// CTA tile 128(m) x 256(n), 8 warps @64x64. grid = (N/256, M/128).
// MODE 0: plain fp32 C[m*1024+n]
// MODE 1: aug scatter ((bb*16+hh)*2048+s)*192 + d
// MODE 2: fp16-split V^T [bh][dk][part][s]
// ---------------------------------------------------------------------------
#define A16B (128 * 80)
#define B16B (256 * 80)

template<int MODE>
__global__ __launch_bounds__(256, 1)
void gemm16_k(const __half* __restrict__ Ae, const __half* __restrict__ Be,
              const float* __restrict__ bias, void* __restrict__ Cv)
{
    extern __shared__ char smc[];

    const int tid  = threadIdx.x;
    const int wid  = tid >> 5;
    const int lane = tid & 31;
    const int g    = lane >> 2;
    const int tig  = lane & 3;
    const int wm   = wid >> 2;
    const int wn   = wid & 3;

    const int m0 = blockIdx.y * 128;
    const int n0 = blockIdx.x * 256;

    const __half* Ag = Ae + (size_t)m0 * XEXT;
    const __half* Bg = Be + (size_t)n0 * XEXT;

    const int lrow = tid >> 3;
    const int t8   = tid & 7;

    float acc[4][8][4];
#pragma unroll
    for (int mf = 0; mf < 4; mf++)
#pragma unroll
        for (int nf = 0; nf < 8; nf++)
#pragma unroll
            for (int j = 0; j < 4; j++) acc[mf][nf][j] = 0.f;

    uint2 ra[4], rb[8];
    auto ldg = [&](int c) {
#pragma unroll
        for (int i = 0; i < 4; i++)
            ra[i] = *(const uint2*)(Ag + (size_t)(lrow + i * 32) * XEXT + c * 32 + t8 * 4);
#pragma unroll
        for (int i = 0; i < 8; i++)
            rb[i] = *(const uint2*)(Bg + (size_t)(lrow + i * 32) * XEXT + c * 32 + t8 * 4);
    };
    auto sts = [&](int b) {
        char* a16 = smc + b * A16B;
#pragma unroll
        for (int i = 0; i < 4; i++)
            *(uint2*)(a16 + (lrow + i * 32) * 80 + t8 * 8) = ra[i];
        char* b16 = smc + 2 * A16B + b * B16B;
#pragma unroll
        for (int i = 0; i < 8; i++)
            *(uint2*)(b16 + (lrow + i * 32) * 80 + t8 * 8) = rb[i];
    };

    ldg(0);
    sts(0);
    __syncthreads();

    const int NCH = XEXT / 32;   // 96
    for (int c = 0; c < NCH; c++) {
        int buf = c & 1;
        if (c + 1 < NCH) ldg(c + 1);

        const char* a16 = smc + buf * A16B + (wm * 64) * 80;
        const char* b16 = smc + 2 * A16B + buf * B16B + (wn * 64) * 80;
#pragma unroll
        for (int st = 0; st < 2; st++) {
            int kb = st * 32;
            uint32_t bfr[8][2];
#pragma unroll
            for (int nf = 0; nf < 8; nf++) {
                const char* br = b16 + (nf * 8 + g) * 80 + kb + tig * 4;
                bfr[nf][0] = *(const uint32_t*)br;
                bfr[nf][1] = *(const uint32_t*)(br + 16);
            }
#pragma unroll
            for (int mf = 0; mf < 4; mf++) {
                const char* ar = a16 + (mf * 16 + g) * 80 + kb + tig * 4;
                uint32_t afr[4];
                afr[0] = *(const uint32_t*)ar;
                afr[1] = *(const uint32_t*)(ar + 8 * 80);
                afr[2] = *(const uint32_t*)(ar + 16);
                afr[3] = *(const uint32_t*)(ar + 8 * 80 + 16);
#pragma unroll
                for (int nf = 0; nf < 8; nf++)
                    mma_fp16(acc[mf][nf], afr, bfr[nf]);
            }
        }
        if (c + 1 < NCH) sts(buf ^ 1);
        __syncthreads();
    }

    // epilogue
#pragma unroll
    for (int mf = 0; mf < 4; mf++) {
        int row0 = m0 + wm * 64 + mf * 16 + g;
#pragma unroll
        for (int nf = 0; nf < 8; nf++) {
            int n = n0 + wn * 64 + nf * 8 + tig * 2;
            float bx = bias[n], by = bias[n + 1];
#pragma unroll
            for (int hf = 0; hf < 2; hf++) {
                int m = row0 + hf * 8;
                float vx = acc[mf][nf][hf * 2] + bx;
                float vy = acc[mf][nf][hf * 2 + 1] + by;
                if (MODE == 0) {
                    *(float2*)((float*)Cv + (size_t)m * Dd + n) = make_float2(vx, vy);
                } else if (MODE == 1) {
                    int bb = m >> 11, s = m & 2047;
                    int hh = n >> 6,  d = n & 63;
                    *(float2*)((float*)Cv +
                        ((size_t)((bb * 16 + hh) * 2048 + s)) * AUGC + d) =
                        make_float2(vx, vy);
                } else {
                    int bb = m >> 11, s = m & 2047;
                    int hh = n >> 6,  d = n & 63;
                    __half* vp = (__half*)Cv
                        + (((size_t)(bb * 16 + hh) * 64 + d) * 2) * 2048 + s;
                    __half h0 = __float2half_rn(vx);
                    vp[0]    = h0;
                    vp[2048] = __float2half_rn(vx - __half2float(h0));
                    __half h1 = __float2half_rn(vy);
                    vp[2 * 2048] = h1;
                    vp[3 * 2048] = __float2half_rn(vy - __half2float(h1));
                }
            }
        }
    }
}

// ---------------------------------------------------------------------------
// FFT (known-good)
// ---------------------------------------------------------------------------
__global__ __launch_bounds__(256)
void fft_k(float* qaug, float* kaug, const float* twp, const float* fwp)
{
    __shared__ float  sr[2][2048];
    __shared__ float  si[2][2048];
    __shared__ float2 tw[1024];

    int bh     = blockIdx.x;
    int tensor = blockIdx.y;
    int dk0    = blockIdx.z * 2;
    float* base = (tensor == 0 ? qaug : kaug) + (size_t)bh * Ss * AUGC;
    int tid = threadIdx.x;

    for (int t = tid; t < 1024; t += 256) tw[t] = g_twid[t];

    for (int idx = tid; idx < 2 * Ss; idx += 256) {
        int l = idx & 1;
        int s = idx >> 1;
        float v = base[(size_t)s * AUGC + dk0 + l];
        int rs = __brev((unsigned)s) >> 21;
        sr[l][rs] = v;
        si[l][rs] = 0.f;
    }
    __syncthreads();

    for (int len = 2; len <= 2048; len <<= 1) {
        int half = len >> 1;
        int step = 2048 / len;
        for (int idx = tid; idx < 2048; idx += 256) {
            int l   = idx >> 10;
            int bix = idx & 1023;
            int grp = bix / half;
            int pos = bix - grp * half;
            int i0 = grp * len + pos;
            int i1 = i0 + half;
            float2 w = tw[pos * step];
            float xr = sr[l][i1], xi = si[l][i1];
            float tr = xr * w.x - xi * w.y;
            float ti = xr * w.y + xi * w.x;
            float ur = sr[l][i0], ui = si[l][i0];
            sr[l][i0] = ur + tr;  si[l][i0] = ui + ti;
            sr[l][i1] = ur - tr;  si[l][i1] = ui - ti;
        }
        __syncthreads();
    }

    float ft, ff;
    if (tensor == 0) { ft = twp[0] * 0.125f; ff = fwp[0] * 0.125f; }
    else             { ft = 1.f;             ff = 1.f; }

    for (int idx = tid; idx < 2 * Ss; idx += 256) {
        int l = idx & 1;
        int s = idx >> 1;
        size_t o = (size_t)s * AUGC + dk0 + l;
        if (tensor == 0) base[o] *= ft;
        base[o + 64]  = sr[l][s] * ff;
        base[o + 128] = si[l][s] * ff;
    }
}

// ---------------------------------------------------------------------------
// Convert aug (192 f32) -> fp16x2 ext (576 fp16)
// ---------------------------------------------------------------------------
template<int QMODE>
__global__ __launch_bounds__(256)
void convert16_k(const float* __restrict__ src, __half* __restrict__ dst)
{
    size_t i4 = (size_t)blockIdx.x * 256 + threadIdx.x;
    size_t row = i4 / 48;
    int c4 = (int)(i4 % 48);
    float4 x = ((const float4*)src)[i4];

    __half hx = __float2half_rn(x.x), hy = __float2half_rn(x.y);
    __half hz = __float2half_rn(x.z), hw = __float2half_rn(x.w);
    __half lx = __float2half_rn(x.x - __half2float(hx));
    __half ly = __float2half_rn(x.y - __half2float(hy));
    __half lz = __float2half_rn(x.z - __half2float(hz));
    __half lw = __float2half_rn(x.w - __half2float(hw));

    uint2 H, L;
    H.x = packh2(hx, hy); H.y = packh2(hz, hw);
    L.x = packh2(lx, ly); L.y = packh2(lz, lw);

    __half* drow = dst + row * ECOLS;
    int base, f, span;
    if (c4 < 16) { base = 0;   f = c4 * 4;      span = 64;  }
    else         { base = 192; f = c4 * 4 - 64; span = 128; }

    *(uint2*)(drow + base + f) = H;
    if (QMODE) {
        *(uint2*)(drow + base + span + f)     = L;
        *(uint2*)(drow + base + 2 * span + f) = H;
    } else {
        *(uint2*)(drow + base + span + f)     = H;
        *(uint2*)(drow + base + 2 * span + f) = L;
    }
}

// ---------------------------------------------------------------------------
// fp16 mma scores (known-good from R7)
// ---------------------------------------------------------------------------
template<int KOFF, int NCH, int EPI>
__global__ __launch_bounds__(256, 1)
void scores16_k(const __half* __restrict__ Qe, const __half* __restrict__ Ke,
                float* __restrict__ attn, float* __restrict__ Freq,
                float* __restrict__ pmax, float* __restrict__ psum)
{
    extern __shared__ char smc[];

    const int tid  = threadIdx.x;
    const int wid  = tid >> 5;
    const int lane = tid & 31;
    const int g    = lane >> 2;
    const int tig  = lane & 3;
    const int wm   = wid >> 2;
    const int wn   = wid & 3;

    const int ntile = blockIdx.x;
    const int mtile = blockIdx.y;
    const int bh    = blockIdx.z;
    const int m0 = mtile * 128;
    const int n0 = ntile * 256;

    const __half* Ag = Qe + ((size_t)bh * Ss + m0) * ECOLS + KOFF;
    const __half* Bg = Ke + ((size_t)bh * Ss + n0) * ECOLS + KOFF;

    const int lrow = tid >> 3;
    const int t8   = tid & 7;

    float acc[4][8][4];
#pragma unroll
    for (int mf = 0; mf < 4; mf++)
#pragma unroll
        for (int nf = 0; nf < 8; nf++)
#pragma unroll
            for (int j = 0; j < 4; j++) acc[mf][nf][j] = 0.f;

    uint2 ra[4], rb[8];
    auto ldg = [&](int c) {
#pragma unroll
        for (int i = 0; i < 4; i++)
            ra[i] = *(const uint2*)(Ag + (size_t)(lrow + i * 32) * ECOLS + c * 32 + t8 * 4);
#pragma unroll
        for (int i = 0; i < 8; i++)
            rb[i] = *(const uint2*)(Bg + (size_t)(lrow + i * 32) * ECOLS + c * 32 + t8 * 4);
    };
    auto sts = [&](int b) {
        char* a16 = smc + b * A16B;
#pragma unroll
        for (int i = 0; i < 4; i++)
            *(uint2*)(a16 + (lrow + i * 32) * 80 + t8 * 8) = ra[i];
        char* b16 = smc + 2 * A16B + b * B16B;
#pragma unroll
        for (int i = 0; i < 8; i++)
            *(uint2*)(b16 + (lrow + i * 32) * 80 + t8 * 8) = rb[i];
    };

    ldg(0);
    sts(0);
    __syncthreads();

    for (int c = 0; c < NCH; c++) {
        int buf = c & 1;
        if (c + 1 < NCH) ldg(c + 1);

        const char* a16 = smc + buf * A16B + (wm * 64) * 80;
        const char* b16 = smc + 2 * A16B + buf * B16B + (wn * 64) * 80;
#pragma unroll
        for (int st = 0; st < 2; st++) {
            int kb = st * 32;
            uint32_t bfr[8][2];
#pragma unroll
            for (int nf = 0; nf < 8; nf++) {
                const char* br = b16 + (nf * 8 + g) * 80 + kb + tig * 4;
                bfr[nf][0] = *(const uint32_t*)br;
                bfr[nf][1] = *(const uint32_t*)(br + 16);
            }
#pragma unroll
            for (int mf = 0; mf < 4; mf++) {
                const char* ar = a16 + (mf * 16 + g) * 80 + kb + tig * 4;
                uint32_t afr[4];
                afr[0] = *(const uint32_t*)ar;
                afr[1] = *(const uint32_t*)(ar + 8 * 80);
                afr[2] = *(const uint32_t*)(ar + 16);
                afr[3] = *(const uint32_t*)(ar + 8 * 80 + 16);
#pragma unroll
                for (int nf = 0; nf < 8; nf++)
                    mma_fp16(acc[mf][nf], afr, bfr[nf]);
            }
        }
        if (c + 1 < NCH) sts(buf ^ 1);
        __syncthreads();
    }

    const int cbase = n0 + wn * 64 + tig * 2;

    if (EPI == 0) {
#pragma unroll
        for (int mf = 0; mf < 4; mf++) {
            int r0 = m0 + wm * 64 + mf * 16 + g;
#pragma unroll
            for (int hf = 0; hf < 2; hf++) {
                int r = r0 + hf * 8;
                if (r <= 1024) {
                    float* frow = Freq + ((size_t)bh * 1025 + r) * Ss;
#pragma unroll
                    for (int nf = 0; nf < 8; nf++)
                        *(float2*)(frow + cbase + nf * 8) =
                            make_float2(acc[mf][nf][hf * 2], acc[mf][nf][hf * 2 + 1]);
                }
            }
        }
    } else {
#pragma unroll
        for (int mf = 0; mf < 4; mf++) {
            int row0 = m0 + wm * 64 + mf * 16 + g;
#pragma unroll
            for (int hf = 0; hf < 2; hf++) {
                int r = row0 + hf * 8;
                if (r <= 1024) {
                    const float* fr = Freq + ((size_t)bh * 1025 + r) * Ss;
#pragma unroll
                    for (int nf = 0; nf < 8; nf++) {
                        float2 f = *(const float2*)(fr + cbase + nf * 8);
                        acc[mf][nf][hf * 2]     += f.x;
                        acc[mf][nf][hf * 2 + 1] += f.y;
                    }
                } else {
                    const float* fr = Freq + ((size_t)bh * 1025 + (2048 - r)) * Ss;
#pragma unroll
                    for (int nf = 0; nf < 8; nf++) {
                        int c0 = cbase + nf * 8;
                        acc[mf][nf][hf * 2]     += fr[(2048 - c0) & 2047];
                        acc[mf][nf][hf * 2 + 1] += fr[2047 - c0];
                    }
                }
            }

            float mx0 = -3.4e38f, mx1 = -3.4e38f;
#pragma unroll
            for (int nf = 0; nf < 8; nf++) {
                mx0 = fmaxf(mx0, fmaxf(acc[mf][nf][0], acc[mf][nf][1]));
                mx1 = fmaxf(mx1, fmaxf(acc[mf][nf][2], acc[mf][nf][3]));
            }
            mx0 = fmaxf(mx0, __shfl_xor_sync(0xffffffffu, mx0, 1));
            mx0 = fmaxf(mx0, __shfl_xor_sync(0xffffffffu, mx0, 2));
            mx1 = fmaxf(mx1, __shfl_xor_sync(0xffffffffu, mx1, 1));
            mx1 = fmaxf(mx1, __shfl_xor_sync(0xffffffffu, mx1, 2));

            float s0 = 0.f, s1 = 0.f;
#pragma unroll
            for (int nf = 0; nf < 8; nf++) {
                s0 += __expf(acc[mf][nf][0] - mx0) + __expf(acc[mf][nf][1] - mx0);
                s1 += __expf(acc[mf][nf][2] - mx1) + __expf(acc[mf][nf][3] - mx1);
            }
            s0 += __shfl_xor_sync(0xffffffffu, s0, 1);
            s0 += __shfl_xor_sync(0xffffffffu, s0, 2);
            s1 += __shfl_xor_sync(0xffffffffu, s1, 1);
            s1 += __shfl_xor_sync(0xffffffffu, s1, 2);

            if (tig == 0) {
                size_t gr0 = ((size_t)bh * Ss + row0) * NPART + ntile * 4 + wn;
                pmax[gr0] = mx0; psum[gr0] = s0;
                size_t gr1 = gr0 + 8 * NPART;
                pmax[gr1] = mx1; psum[gr1] = s1;
            }

            float* arow  = attn + ((size_t)bh << 22) + (size_t)row0 * Ss + cbase;
            float* arow8 = arow + 8 * Ss;
#pragma unroll
            for (int nf = 0; nf < 8; nf++)
                *(float2*)(arow + nf * 8) = make_float2(acc[mf][nf][0], acc[mf][nf][1]);
#pragma unroll
            for (int nf = 0; nf < 8; nf++)
                *(float2*)(arow8 + nf * 8) = make_float2(acc[mf][nf][2], acc[mf][nf][3]);
        }
    }
}

// ---------------------------------------------------------------------------
// Combine softmax partials
// ---------------------------------------------------------------------------
__global__ __launch_bounds__(256)
void combine_k(const float* __restrict__ pmax, const float* __restrict__ psum,
               float* __restrict__ rowm, float* __restrict__ rowz)
{
    int r = blockIdx.x * 256 + threadIdx.x;
    float m = -3.4e38f;
#pragma unroll
    for (int i = 0; i < NPART; i++) m = fmaxf(m, pmax[(size_t)r * NPART + i]);
    float z = 0.f;
#pragma unroll
    for (int i = 0; i < NPART; i++)
        z += psum[(size_t)r * NPART + i] * __expf(pmax[(size_t)r * NPART + i] - m);
    rowm[r] = m;
    rowz[r] = 1.f / z;
}

// ---------------------------------------------------------------------------
// Fused normalize + attn*V; epilogue emits O in fp16 3-term ext layout.
// ---------------------------------------------------------------------------
#define AVA (128 * 80)
#define AVB (64 * 80)

__global__ __launch_bounds__(256, 1)
void attnv16_k(float* __restrict__ attn, const __half* __restrict__ V16,
               const float* __restrict__ rowm, const float* __restrict__ rowz,
               __half* __restrict__ Oe)
{
    __shared__ char smc[2 * AVA + 2 * AVB];

    const int tid  = threadIdx.x;
    const int wid  = tid >> 5;
    const int lane = tid & 31;
    const int g    = lane >> 2;
    const int tig  = lane & 3;
    const int wm   = wid & 3;
    const int wn   = wid >> 2;

    const int mt = blockIdx.x, bh = blockIdx.y;
    const int m0 = mt * 128;
    float* Ab = attn + ((size_t)bh << 22) + (size_t)m0 * Ss;
    const __half* Vb = V16 + (size_t)bh * 128 * 2048;

    const int prow = tid >> 2;
    const int pf4  = tid & 3;
    const float rm0 = rowm[bh * Ss + m0 + prow];
    const float rz0 = rowz[bh * Ss + m0 + prow];
    const float rm1 = rowm[bh * Ss + m0 + prow + 64];
    const float rz1 = rowz[bh * Ss + m0 + prow + 64];

    const int bseg  = tid >> 1;
    const int bn    = bseg & 63;
    const int bpart = bseg >> 6;
    const int bh16  = tid & 1;

    float acc[2][4][4];
#pragma unroll
    for (int mf = 0; mf < 2; mf++)
#pragma unroll
        for (int nf = 0; nf < 4; nf++)
#pragma unroll
            for (int j = 0; j < 4; j++) acc[mf][nf][j] = 0.f;

    float4 pa[2];
    uint4  vb;

    auto ldg = [&](int c) {
        pa[0] = *(const float4*)(Ab + (size_t)prow * Ss + c * 16 + pf4 * 4);
        pa[1] = *(const float4*)(Ab + (size_t)(prow + 64) * Ss + c * 16 + pf4 * 4);
        vb = *(const uint4*)(Vb + ((size_t)bn * 2 + bpart) * 2048 + c * 16 + bh16 * 8);
    };
    auto sts = [&](int b, int c) {
        char* a16 = smc + b * AVA;
#pragma unroll
        for (int i = 0; i < 2; i++) {
            float rm = i ? rm1 : rm0, rz = i ? rz1 : rz0;
            float4 p;
            p.x = __expf(pa[i].x - rm) * rz;
            p.y = __expf(pa[i].y - rm) * rz;
            p.z = __expf(pa[i].z - rm) * rz;
            p.w = __expf(pa[i].w - rm) * rz;
            *(float4*)(Ab + (size_t)(prow + i * 64) * Ss + c * 16 + pf4 * 4) = p;
            uint2 hp;
            hp.x = packh2(__float2half_rn(p.x), __float2half_rn(p.y));
            hp.y = packh2(__float2half_rn(p.z), __float2half_rn(p.w));
            char* arow = a16 + (prow + i * 64) * 80;
            *(uint2*)(arow + pf4 * 8)      = hp;
            *(uint2*)(arow + 32 + pf4 * 8) = hp;
        }
        char* b16 = smc + 2 * AVA + b * AVB;
        *(uint4*)(b16 + bn * 80 + bpart * 32 + bh16 * 16) = vb;
    };

    ldg(0);
    sts(0, 0);
    __syncthreads();

    const int NCH = 128;
    for (int c = 0; c < NCH; c++) {
        int buf = c & 1;
        if (c + 1 < NCH) ldg(c + 1);

        const char* a16 = smc + buf * AVA + (wm * 32) * 80;
        const char* b16 = smc + 2 * AVA + buf * AVB + (wn * 32) * 80;
#pragma unroll
        for (int st = 0; st < 2; st++) {
            int kb = st * 32;
            uint32_t bfr[4][2];
#pragma unroll
            for (int nf = 0; nf < 4; nf++) {
                const char* br = b16 + (nf * 8 + g) * 80 + kb + tig * 4;
                bfr[nf][0] = *(const uint32_t*)br;
                bfr[nf][1] = *(const uint32_t*)(br + 16);
            }
#pragma unroll
            for (int mf = 0; mf < 2; mf++) {
                const char* ar = a16 + (mf * 16 + g) * 80 + kb + tig * 4;
                uint32_t afr[4];
                afr[0] = *(const uint32_t*)ar;
                afr[1] = *(const uint32_t*)(ar + 8 * 80);
                afr[2] = *(const uint32_t*)(ar + 16);
                afr[3] = *(const uint32_t*)(ar + 8 * 80 + 16);
#pragma unroll
                for (int nf = 0; nf < 4; nf++)
                    mma_fp16(acc[mf][nf], afr, bfr[nf]);
            }
        }
        if (c + 1 < NCH) sts(buf ^ 1, c + 1);
        __syncthreads();
    }

    // epilogue: O -> ext fp16 [oh|ol|oh], row = b*2048+s, col = h*64+dk
    size_t rowbase = (size_t)(bh >> 4) * Ss + m0;
    int colbase = (bh & 15) * 64;
#pragma unroll
    for (int mf = 0; mf < 2; mf++) {
        int r0 = wm * 32 + mf * 16 + g;
#pragma unroll
        for (int nf = 0; nf < 4; nf++) {
            int col = colbase + wn * 32 + nf * 8 + tig * 2;
#pragma unroll
            for (int hf = 0; hf < 2; hf++) {
                float vx = acc[mf][nf][hf * 2], vy = acc[mf][nf][hf * 2 + 1];
                __half hx = __float2half_rn(vx), hy = __float2half_rn(vy);
                uint32_t H = packh2(hx, hy);
                uint32_t L = packh2(__float2half_rn(vx - __half2float(hx)),
                                    __float2half_rn(vy - __half2float(hy)));
                __half* orow = Oe + (rowbase + r0 + hf * 8) * XEXT;
                *(uint32_t*)(orow + col)        = H;
                *(uint32_t*)(orow + 1024 + col) = L;
                *(uint32_t*)(orow + 2048 + col) = H;
            }
        }
    }
}

// ---------------------------------------------------------------------------
extern "C" void kernel_launch(void* const* d_in, const int* in_sizes, int n_in,
                              void* d_out, int out_size)
{
    const float* x  = (const float*)d_in[0];
    const float* Wq = (const float*)d_in[1];
    const float* bq = (const float*)d_in[2];
    const float* Wk = (const float*)d_in[3];
    const float* bk = (const float*)d_in[4];
    const float* Wv = (const float*)d_in[5];
    const float* bv = (const float*)d_in[6];
    const float* Wo = (const float*)d_in[7];
    const float* bo = (const float*)d_in[8];
    const float* tw = (const float*)d_in[9];
    const float* fw = (const float*)d_in[10];

    float* out  = (float*)d_out;
    float* attn = out + (size_t)Mm * Dd;

    float *qaug, *kaug, *freq, *pmax, *psum, *rowm, *rowz;
    __half *qe, *ke, *v16, *xe, *wq16, *wk16, *wv16, *wo16, *oe;
    cudaGetSymbolAddress((void**)&qaug, g_Qaug);
    cudaGetSymbolAddress((void**)&kaug, g_Kaug);
    cudaGetSymbolAddress((void**)&qe,   g_Qe16);
    cudaGetSymbolAddress((void**)&ke,   g_Ke16);
    cudaGetSymbolAddress((void**)&v16,  g_V16);
    cudaGetSymbolAddress((void**)&freq, g_Freq);
    cudaGetSymbolAddress((void**)&xe,   g_Xext);
    cudaGetSymbolAddress((void**)&wq16, g_Wq16);
    cudaGetSymbolAddress((void**)&wk16, g_Wk16);
    cudaGetSymbolAddress((void**)&wv16, g_Wv16);
    cudaGetSymbolAddress((void**)&wo16, g_Wo16);
    cudaGetSymbolAddress((void**)&oe,   g_Oext);
    cudaGetSymbolAddress((void**)&pmax, g_pmax);
    cudaGetSymbolAddress((void**)&psum, g_psum);
    cudaGetSymbolAddress((void**)&rowm, g_rowm);
    cudaGetSymbolAddress((void**)&rowz, g_rowz);

    static const int SM16 = 2 * A16B + 2 * B16B;   // 61440
    cudaFuncSetAttribute(scores16_k<192, 12, 0>,
                         cudaFuncAttributeMaxDynamicSharedMemorySize, SM16);
    cudaFuncSetAttribute(scores16_k<0, 6, 1>,
                         cudaFuncAttributeMaxDynamicSharedMemorySize, SM16);
    cudaFuncSetAttribute(gemm16_k<0>, cudaFuncAttributeMaxDynamicSharedMemorySize, SM16);
    cudaFuncSetAttribute(gemm16_k<1>, cudaFuncAttributeMaxDynamicSharedMemorySize, SM16);
    cudaFuncSetAttribute(gemm16_k<2>, cudaFuncAttributeMaxDynamicSharedMemorySize, SM16);

    dim3 blk(256);

    twiddle_init_k<<<4, 256>>>();

    // ext conversions (x activation-style, weights weight-style)
    convext_k<0><<<Mm, 256>>>(x, xe);          // 4096 rows x 256 f4
    convext_k<1><<<Dd, 256>>>(Wq, wq16);
    convext_k<1><<<Dd, 256>>>(Wk, wk16);
    convext_k<1><<<Dd, 256>>>(Wv, wv16);
    convext_k<1><<<Dd, 256>>>(Wo, wo16);

    // projections on fp16 mma (3-term)
    gemm16_k<1><<<dim3(4, 32), blk, SM16>>>(xe, wq16, bq, qaug);
    gemm16_k<1><<<dim3(4, 32), blk, SM16>>>(xe, wk16, bk, kaug);
    gemm16_k<2><<<dim3(4, 32), blk, SM16>>>(xe, wv16, bv, v16);

    // FFT
    fft_k<<<dim3(BHh, 2, 32), blk>>>(qaug, kaug, tw, fw);

    // fp16x2 split for scores
    {
        int nblk = (int)(((size_t)BHh * Ss * 48) / 256);
        convert16_k<1><<<nblk, 256>>>(qaug, qe);
        convert16_k<0><<<nblk, 256>>>(kaug, ke);
    }

    // freq scores rows 0..1024 -> staged
    scores16_k<192, 12, 0><<<dim3(8, 9, BHh), blk, SM16>>>(qe, ke, attn, freq, pmax, psum);

    // time scores + freq add + softmax partials
    scores16_k<0, 6, 1><<<dim3(8, 16, BHh), blk, SM16>>>(qe, ke, attn, freq, pmax, psum);

    // combine partials
    combine_k<<<(BHh * Ss) / 256, 256>>>(pmax, psum, rowm, rowz);

    // fused normalize + attn*V -> O ext fp16
    attnv16_k<<<dim3(16, BHh), blk>>>(attn, v16, rowm, rowz, oe);

    // out projection on fp16 mma
    gemm16_k<0><<<dim3(4, 32), blk, SM16>>>(oe, wo16, bo, out);
}

// round 9
// speedup vs baseline: 1.6639x; 1.0449x over previous
#include <cuda_runtime.h>
#include <cuda_fp16.h>
#include <math.h>
#include <stdint.h>

// Problem constants
#define Bb   2
#define Ss   2048
#define Dd   1024
#define Hh   16
#define DKk  64
#define AUGC 192              // [time(64) | Re(64) | Im(64)]
#define ECOLS 576             // fp16 ext: [time 3x64 | freq 3x128]
#define XEXT 3072             // fp16 3-term ext for D=1024 GEMMs
#define BHh  (Bb * Hh)        // 32
#define Mm   (Bb * Ss)        // 4096
#define NPART 32

// Scratch
__device__ float   g_Qaug[(size_t)BHh * Ss * AUGC];
__device__ float   g_Kaug[(size_t)BHh * Ss * AUGC];
__device__ __half  g_Qe16[(size_t)BHh * Ss * ECOLS];
__device__ __half  g_Ke16[(size_t)BHh * Ss * ECOLS];
__device__ __half  g_V16 [(size_t)BHh * DKk * Ss];       // [bh][dk][s], single fp16
__device__ float   g_Freq[(size_t)BHh * 1025 * Ss];      // staged freq rows 0..1024
__device__ __half  g_Xext[(size_t)Mm * XEXT];            // [xh|xl|xh]
__device__ __half  g_W16 [4][(size_t)Dd * XEXT];         // q,k,v,o: [Wh|Wh|Wl]
__device__ __half  g_Oext[(size_t)Mm * XEXT];            // [oh|ol|oh]
__device__ float   g_pmax[(size_t)BHh * Ss * NPART];
__device__ float   g_psum[(size_t)BHh * Ss * NPART];
__device__ float   g_rowm[(size_t)BHh * Ss];
__device__ float   g_rowz[(size_t)BHh * Ss];
__device__ float2  g_twid[1024];

// ---------------------------------------------------------------------------
__device__ __forceinline__ uint32_t packh2(__half a, __half b) {
    __half2 p = __halves2half2(a, b);
    return *reinterpret_cast<uint32_t*>(&p);
}
__device__ __forceinline__ void mma_fp16(float c[4], const uint32_t a[4],
                                         const uint32_t b[2]) {
    asm volatile(
        "mma.sync.aligned.m16n8k16.row.col.f32.f16.f16.f32 "
        "{%0,%1,%2,%3}, {%4,%5,%6,%7}, {%8,%9}, {%0,%1,%2,%3};"
        : "+f"(c[0]), "+f"(c[1]), "+f"(c[2]), "+f"(c[3])
        : "r"(a[0]), "r"(a[1]), "r"(a[2]), "r"(a[3]), "r"(b[0]), "r"(b[1]));
}

// ---------------------------------------------------------------------------
__global__ void twiddle_init_k() {
    int t = blockIdx.x * blockDim.x + threadIdx.x;
    if (t < 1024) {
        double ang = -2.0 * 3.14159265358979323846 * (double)t / 2048.0;
        double s, c;
        sincos(ang, &s, &c);
        g_twid[t] = make_float2((float)c, (float)s);
    }
}

// ---------------------------------------------------------------------------
// f32 -> fp16 3-term ext. Activation x: [h|l|h], grid (Mm).
// ---------------------------------------------------------------------------
__global__ __launch_bounds__(256)
void convx_k(const float* __restrict__ src, __half* __restrict__ dst)
{
    size_t i4 = (size_t)blockIdx.x * 256 + threadIdx.x;
    size_t row = i4 >> 8;
    int c = (int)(i4 & 255) * 4;
    float4 x = ((const float4*)src)[i4];

    __half hx = __float2half_rn(x.x), hy = __float2half_rn(x.y);
    __half hz = __float2half_rn(x.z), hw = __float2half_rn(x.w);
    uint2 H, L;
    H.x = packh2(hx, hy); H.y = packh2(hz, hw);
    L.x = packh2(__float2half_rn(x.x - __half2float(hx)),
                 __float2half_rn(x.y - __half2float(hy)));
    L.y = packh2(__float2half_rn(x.z - __half2float(hz)),
                 __float2half_rn(x.w - __half2float(hw)));

    __half* d = dst + row * XEXT;
    *(uint2*)(d + c) = H;
    *(uint2*)(d + 1024 + c) = L;
    *(uint2*)(d + 2048 + c) = H;
}

// Weights (all 4 in one launch, z selects): [h|h|l]
__global__ __launch_bounds__(256)
void convw_k(const float* __restrict__ Wq, const float* __restrict__ Wk,
             const float* __restrict__ Wv, const float* __restrict__ Wo)
{
    int z = blockIdx.y;
    const float* src = (z == 0) ? Wq : (z == 1) ? Wk : (z == 2) ? Wv : Wo;
    __half* dst = g_W16[z];

    size_t i4 = (size_t)blockIdx.x * 256 + threadIdx.x;
    size_t row = i4 >> 8;
    int c = (int)(i4 & 255) * 4;
    float4 x = ((const float4*)src)[i4];

    __half hx = __float2half_rn(x.x), hy = __float2half_rn(x.y);
    __half hz = __float2half_rn(x.z), hw = __float2half_rn(x.w);
    uint2 H, L;
    H.x = packh2(hx, hy); H.y = packh2(hz, hw);
    L.x = packh2(__float2half_rn(x.x - __half2float(hx)),
                 __float2half_rn(x.y - __half2float(hy)));
    L.y = packh2(__float2half_rn(x.z - __half2float(hz)),
                 __float2half_rn(x.w - __half2float(hw)));

    __half* d = dst + row * XEXT;
    *(uint2*)(d + c) = H;
    *(uint2*)(d + 1024 + c) = H;
    *(uint2*)(d + 2048 + c) = L;
}

// ---------------------------------------------------------------------------
// fp16 3-term GEMM core (macro body shared by the QKV-merged and O kernels).
// CTA tile 128(m) x 256(n), 8 warps @64x64, K=3072 (96 chunks of 32).
// ---------------------------------------------------------------------------
#define A16B (128 * 80)
#define B16B (256 * 80)

// Merged Q/K/V projection: grid (4, 32, 3); z=0 Q->qaug, z=1 K->kaug, z=2 V->v16
__global__ __launch_bounds__(256, 1)
void gemm16qkv_k(const __half* __restrict__ Xe,
                 const float* __restrict__ bq, const float* __restrict__ bk,
                 const float* __restrict__ bv,
                 float* __restrict__ qaug, float* __restrict__ kaug,
                 __half* __restrict__ v16)
{
    extern __shared__ char smc[];

    const int tid  = threadIdx.x;
    const int wid  = tid >> 5;
    const int lane = tid & 31;
    const int g    = lane >> 2;
    const int tig  = lane & 3;
    const int wm   = wid >> 2;
    const int wn   = wid & 3;

    const int z  = blockIdx.z;
    const int m0 = blockIdx.y * 128;
    const int n0 = blockIdx.x * 256;

    const __half* Ag = Xe + (size_t)m0 * XEXT;
    const __half* Bg = g_W16[z] + (size_t)n0 * XEXT;
    const float* bias = (z == 0) ? bq : (z == 1) ? bk : bv;

    const int lrow = tid >> 3;
    const int t8   = tid & 7;

    float acc[4][8][4];
#pragma unroll
    for (int mf = 0; mf < 4; mf++)
#pragma unroll
        for (int nf = 0; nf < 8; nf++)
#pragma unroll
            for (int j = 0; j < 4; j++) acc[mf][nf][j] = 0.f;

    uint2 ra[4], rb[8];
    auto ldg = [&](int c) {
#pragma unroll
        for (int i = 0; i < 4; i++)
            ra[i] = *(const uint2*)(Ag + (size_t)(lrow + i * 32) * XEXT + c * 32 + t8 * 4);
#pragma unroll
        for (int i = 0; i < 8; i++)
            rb[i] = *(const uint2*)(Bg + (size_t)(lrow + i * 32) * XEXT + c * 32 + t8 * 4);
    };
    auto sts = [&](int b) {
        char* a16 = smc + b * A16B;
#pragma unroll
        for (int i = 0; i < 4; i++)
            *(uint2*)(a16 + (lrow + i * 32) * 80 + t8 * 8) = ra[i];
        char* b16 = smc + 2 * A16B + b * B16B;
#pragma unroll
        for (int i = 0; i < 8; i++)
            *(uint2*)(b16 + (lrow + i * 32) * 80 + t8 * 8) = rb[i];
    };

    ldg(0);
    sts(0);
    __syncthreads();

    const int NCH = XEXT / 32;
    for (int c = 0; c < NCH; c++) {
        int buf = c & 1;
        if (c + 1 < NCH) ldg(c + 1);

        const char* a16 = smc + buf * A16B + (wm * 64) * 80;
        const char* b16 = smc + 2 * A16B + buf * B16B + (wn * 64) * 80;
#pragma unroll
        for (int st = 0; st < 2; st++) {
            int kb = st * 32;
            uint32_t bfr[8][2];
#pragma unroll
            for (int nf = 0; nf < 8; nf++) {
                const char* br = b16 + (nf * 8 + g) * 80 + kb + tig * 4;
                bfr[nf][0] = *(const uint32_t*)br;
                bfr[nf][1] = *(const uint32_t*)(br + 16);
            }
#pragma unroll
            for (int mf = 0; mf < 4; mf++) {
                const char* ar = a16 + (mf * 16 + g) * 80 + kb + tig * 4;
                uint32_t afr[4];
                afr[0] = *(const uint32_t*)ar;
                afr[1] = *(const uint32_t*)(ar + 8 * 80);
                afr[2] = *(const uint32_t*)(ar + 16);
                afr[3] = *(const uint32_t*)(ar + 8 * 80 + 16);
#pragma unroll
                for (int nf = 0; nf < 8; nf++)
                    mma_fp16(acc[mf][nf], afr, bfr[nf]);
            }
        }
        if (c + 1 < NCH) sts(buf ^ 1);
        __syncthreads();
    }

#pragma unroll
    for (int mf = 0; mf < 4; mf++) {
        int row0 = m0 + wm * 64 + mf * 16 + g;
#pragma unroll
        for (int nf = 0; nf < 8; nf++) {
            int n = n0 + wn * 64 + nf * 8 + tig * 2;
            float bx = bias[n], by = bias[n + 1];
#pragma unroll
            for (int hf = 0; hf < 2; hf++) {
                int m = row0 + hf * 8;
                float vx = acc[mf][nf][hf * 2] + bx;
                float vy = acc[mf][nf][hf * 2 + 1] + by;
                int bb = m >> 11, s = m & 2047;
                int hh = n >> 6,  d = n & 63;
                if (z < 2) {
                    float* aug = (z == 0) ? qaug : kaug;
                    *(float2*)(aug +
                        ((size_t)((bb * 16 + hh) * 2048 + s)) * AUGC + d) =
                        make_float2(vx, vy);
                } else {
                    __half* vp = v16
                        + ((size_t)(bb * 16 + hh) * 64 + d) * 2048 + s;
                    vp[0]    = __float2half_rn(vx);
                    vp[2048] = __float2half_rn(vy);
                }
            }
        }
    }
}

// Out projection: plain fp32 epilogue
__global__ __launch_bounds__(256, 1)
void gemm16o_k(const __half* __restrict__ Ae, const float* __restrict__ bias,
               float* __restrict__ C)
{
    extern __shared__ char smc[];

    const int tid  = threadIdx.x;
    const int wid  = tid >> 5;
    const int lane = tid & 31;
    const int g    = lane >> 2;
    const int tig  = lane & 3;
    const int wm   = wid >> 2;
    const int wn   = wid & 3;

    const int m0 = blockIdx.y * 128;
    const int n0 = blockIdx.x * 256;

    const __half* Ag = Ae + (size_t)m0 * XEXT;
    const __half* Bg = g_W16[3] + (size_t)n0 * XEXT;

    const int lrow = tid >> 3;
    const int t8   = tid & 7;

    float acc[4][8][4];
#pragma unroll
    for (int mf = 0; mf < 4; mf++)
#pragma unroll
        for (int nf = 0; nf < 8; nf++)
#pragma unroll
            for (int j = 0; j < 4; j++) acc[mf][nf][j] = 0.f;

    uint2 ra[4], rb[8];
    auto ldg = [&](int c) {
#pragma unroll
        for (int i = 0; i < 4; i++)
            ra[i] = *(const uint2*)(Ag + (size_t)(lrow + i * 32) * XEXT + c * 32 + t8 * 4);
#pragma unroll
        for (int i = 0; i < 8; i++)
            rb[i] = *(const uint2*)(Bg + (size_t)(lrow + i * 32) * XEXT + c * 32 + t8 * 4);
    };
    auto sts = [&](int b) {
        char* a16 = smc + b * A16B;
#pragma unroll
        for (int i = 0; i < 4; i++)
            *(uint2*)(a16 + (lrow + i * 32) * 80 + t8 * 8) = ra[i];
        char* b16 = smc + 2 * A16B + b * B16B;
#pragma unroll
        for (int i = 0; i < 8; i++)
            *(uint2*)(b16 + (lrow + i * 32) * 80 + t8 * 8) = rb[i];
    };

    ldg(0);
    sts(0);
    __syncthreads();

    const int NCH = XEXT / 32;
    for (int c = 0; c < NCH; c++) {
        int buf = c & 1;
        if (c + 1 < NCH) ldg(c + 1);

        const char* a16 = smc + buf * A16B + (wm * 64) * 80;
        const char* b16 = smc + 2 * A16B + buf * B16B + (wn * 64) * 80;
#pragma unroll
        for (int st = 0; st < 2; st++) {
            int kb = st * 32;
            uint32_t bfr[8][2];
#pragma unroll
            for (int nf = 0; nf < 8; nf++) {
                const char* br = b16 + (nf * 8 + g) * 80 + kb + tig * 4;
                bfr[nf][0] = *(const uint32_t*)br;
                bfr[nf][1] = *(const uint32_t*)(br + 16);
            }
#pragma unroll
            for (int mf = 0; mf < 4; mf++) {
                const char* ar = a16 + (mf * 16 + g) * 80 + kb + tig * 4;
                uint32_t afr[4];
                afr[0] = *(const uint32_t*)ar;
                afr[1] = *(const uint32_t*)(ar + 8 * 80);
                afr[2] = *(const uint32_t*)(ar + 16);
                afr[3] = *(const uint32_t*)(ar + 8 * 80 + 16);
#pragma unroll
                for (int nf = 0; nf < 8; nf++)
                    mma_fp16(acc[mf][nf], afr, bfr[nf]);
            }
        }
        if (c + 1 < NCH) sts(buf ^ 1);
        __syncthreads();
    }

#pragma unroll
    for (int mf = 0; mf < 4; mf++) {
        int row0 = m0 + wm * 64 + mf * 16 + g;
#pragma unroll
        for (int nf = 0; nf < 8; nf++) {
            int n = n0 + wn * 64 + nf * 8 + tig * 2;
            float bx = bias[n], by = bias[n + 1];
#pragma unroll
            for (int hf = 0; hf < 2; hf++) {
                int m = row0 + hf * 8;
                *(float2*)(C + (size_t)m * Dd + n) =
                    make_float2(acc[mf][nf][hf * 2] + bx,
                                acc[mf][nf][hf * 2 + 1] + by);
            }
        }
    }
}

// ---------------------------------------------------------------------------
// FFT (known-good)
// ---------------------------------------------------------------------------
__global__ __launch_bounds__(256)
void fft_k(float* qaug, float* kaug, const float* twp, const float* fwp)
{
    __shared__ float  sr[2][2048];
    __shared__ float  si[2][2048];
    __shared__ float2 tw[1024];

    int bh     = blockIdx.x;
    int tensor = blockIdx.y;
    int dk0    = blockIdx.z * 2;
    float* base = (tensor == 0 ? qaug : kaug) + (size_t)bh * Ss * AUGC;
    int tid = threadIdx.x;

    for (int t = tid; t < 1024; t += 256) tw[t] = g_twid[t];

    for (int idx = tid; idx < 2 * Ss; idx += 256) {
        int l = idx & 1;
        int s = idx >> 1;
        float v = base[(size_t)s * AUGC + dk0 + l];
        int rs = __brev((unsigned)s) >> 21;
        sr[l][rs] = v;
        si[l][rs] = 0.f;
    }
    __syncthreads();

    for (int len = 2; len <= 2048; len <<= 1) {
        int half = len >> 1;
        int step = 2048 / len;
        for (int idx = tid; idx < 2048; idx += 256) {
            int l   = idx >> 10;
            int bix = idx & 1023;
            int grp = bix / half;
            int pos = bix - grp * half;
            int i0 = grp * len + pos;
            int i1 = i0 + half;
            float2 w = tw[pos * step];
            float xr = sr[l][i1], xi = si[l][i1];
            float tr = xr * w.x - xi * w.y;
            float ti = xr * w.y + xi * w.x;
            float ur = sr[l][i0], ui = si[l][i0];
            sr[l][i0] = ur + tr;  si[l][i0] = ui + ti;
            sr[l][i1] = ur - tr;  si[l][i1] = ui - ti;
        }
        __syncthreads();
    }

    float ft, ff;
    if (tensor == 0) { ft = twp[0] * 0.125f; ff = fwp[0] * 0.125f; }
    else             { ft = 1.f;             ff = 1.f; }

    for (int idx = tid; idx < 2 * Ss; idx += 256) {
        int l = idx & 1;
        int s = idx >> 1;
        size_t o = (size_t)s * AUGC + dk0 + l;
        if (tensor == 0) base[o] *= ft;
        base[o + 64]  = sr[l][s] * ff;
        base[o + 128] = si[l][s] * ff;
    }
}

// ---------------------------------------------------------------------------
// Convert aug (192 f32) -> fp16x2 ext (576 fp16)
// ---------------------------------------------------------------------------
template<int QMODE>
__global__ __launch_bounds__(256)
void convert16_k(const float* __restrict__ src, __half* __restrict__ dst)
{
    size_t i4 = (size_t)blockIdx.x * 256 + threadIdx.x;
    size_t row = i4 / 48;
    int c4 = (int)(i4 % 48);
    float4 x = ((const float4*)src)[i4];

    __half hx = __float2half_rn(x.x), hy = __float2half_rn(x.y);
    __half hz = __float2half_rn(x.z), hw = __float2half_rn(x.w);
    __half lx = __float2half_rn(x.x - __half2float(hx));
    __half ly = __float2half_rn(x.y - __half2float(hy));
    __half lz = __float2half_rn(x.z - __half2float(hz));
    __half lw = __float2half_rn(x.w - __half2float(hw));

    uint2 H, L;
    H.x = packh2(hx, hy); H.y = packh2(hz, hw);
    L.x = packh2(lx, ly); L.y = packh2(lz, lw);

    __half* drow = dst + row * ECOLS;
    int base, f, span;
    if (c4 < 16) { base = 0;   f = c4 * 4;      span = 64;  }
    else         { base = 192; f = c4 * 4 - 64; span = 128; }

    *(uint2*)(drow + base + f) = H;
    if (QMODE) {
        *(uint2*)(drow + base + span + f)     = L;
        *(uint2*)(drow + base + 2 * span + f) = H;
    } else {
        *(uint2*)(drow + base + span + f)     = H;
        *(uint2*)(drow + base + 2 * span + f) = L;
    }
}

// ---------------------------------------------------------------------------
// fp16 mma scores (known-good from R7)
// ---------------------------------------------------------------------------
template<int KOFF, int NCH, int EPI>
__global__ __launch_bounds__(256, 1)
void scores16_k(const __half* __restrict__ Qe, const __half* __restrict__ Ke,
                float* __restrict__ attn, float* __restrict__ Freq,
                float* __restrict__ pmax, float* __restrict__ psum)
{
    extern __shared__ char smc[];

    const int tid  = threadIdx.x;
    const int wid  = tid >> 5;
    const int lane = tid & 31;
    const int g    = lane >> 2;
    const int tig  = lane & 3;
    const int wm   = wid >> 2;
    const int wn   = wid & 3;

    const int ntile = blockIdx.x;
    const int mtile = blockIdx.y;
    const int bh    = blockIdx.z;
    const int m0 = mtile * 128;
    const int n0 = ntile * 256;

    const __half* Ag = Qe + ((size_t)bh * Ss + m0) * ECOLS + KOFF;
    const __half* Bg = Ke + ((size_t)bh * Ss + n0) * ECOLS + KOFF;

    const int lrow = tid >> 3;
    const int t8   = tid & 7;

    float acc[4][8][4];
#pragma unroll
    for (int mf = 0; mf < 4; mf++)
#pragma unroll
        for (int nf = 0; nf < 8; nf++)
#pragma unroll
            for (int j = 0; j < 4; j++) acc[mf][nf][j] = 0.f;

    uint2 ra[4], rb[8];
    auto ldg = [&](int c) {
#pragma unroll
        for (int i = 0; i < 4; i++)
            ra[i] = *(const uint2*)(Ag + (size_t)(lrow + i * 32) * ECOLS + c * 32 + t8 * 4);
#pragma unroll
        for (int i = 0; i < 8; i++)
            rb[i] = *(const uint2*)(Bg + (size_t)(lrow + i * 32) * ECOLS + c * 32 + t8 * 4);
    };
    auto sts = [&](int b) {
        char* a16 = smc + b * A16B;
#pragma unroll
        for (int i = 0; i < 4; i++)
            *(uint2*)(a16 + (lrow + i * 32) * 80 + t8 * 8) = ra[i];
        char* b16 = smc + 2 * A16B + b * B16B;
#pragma unroll
        for (int i = 0; i < 8; i++)
            *(uint2*)(b16 + (lrow + i * 32) * 80 + t8 * 8) = rb[i];
    };

    ldg(0);
    sts(0);
    __syncthreads();

    for (int c = 0; c < NCH; c++) {
        int buf = c & 1;
        if (c + 1 < NCH) ldg(c + 1);

        const char* a16 = smc + buf * A16B + (wm * 64) * 80;
        const char* b16 = smc + 2 * A16B + buf * B16B + (wn * 64) * 80;
#pragma unroll
        for (int st = 0; st < 2; st++) {
            int kb = st * 32;
            uint32_t bfr[8][2];
#pragma unroll
            for (int nf = 0; nf < 8; nf++) {
                const char* br = b16 + (nf * 8 + g) * 80 + kb + tig * 4;
                bfr[nf][0] = *(const uint32_t*)br;
                bfr[nf][1] = *(const uint32_t*)(br + 16);
            }
#pragma unroll
            for (int mf = 0; mf < 4; mf++) {
                const char* ar = a16 + (mf * 16 + g) * 80 + kb + tig * 4;
                uint32_t afr[4];
                afr[0] = *(const uint32_t*)ar;
                afr[1] = *(const uint32_t*)(ar + 8 * 80);
                afr[2] = *(const uint32_t*)(ar + 16);
                afr[3] = *(const uint32_t*)(ar + 8 * 80 + 16);
#pragma unroll
                for (int nf = 0; nf < 8; nf++)
                    mma_fp16(acc[mf][nf], afr, bfr[nf]);
            }
        }
        if (c + 1 < NCH) sts(buf ^ 1);
        __syncthreads();
    }

    const int cbase = n0 + wn * 64 + tig * 2;

    if (EPI == 0) {
#pragma unroll
        for (int mf = 0; mf < 4; mf++) {
            int r0 = m0 + wm * 64 + mf * 16 + g;
#pragma unroll
            for (int hf = 0; hf < 2; hf++) {
                int r = r0 + hf * 8;
                if (r <= 1024) {
                    float* frow = Freq + ((size_t)bh * 1025 + r) * Ss;
#pragma unroll
                    for (int nf = 0; nf < 8; nf++)
                        *(float2*)(frow + cbase + nf * 8) =
                            make_float2(acc[mf][nf][hf * 2], acc[mf][nf][hf * 2 + 1]);
                }
            }
        }
    } else {
#pragma unroll
        for (int mf = 0; mf < 4; mf++) {
            int row0 = m0 + wm * 64 + mf * 16 + g;
#pragma unroll
            for (int hf = 0; hf < 2; hf++) {
                int r = row0 + hf * 8;
                if (r <= 1024) {
                    const float* fr = Freq + ((size_t)bh * 1025 + r) * Ss;
#pragma unroll
                    for (int nf = 0; nf < 8; nf++) {
                        float2 f = *(const float2*)(fr + cbase + nf * 8);
                        acc[mf][nf][hf * 2]     += f.x;
                        acc[mf][nf][hf * 2 + 1] += f.y;
                    }
                } else {
                    const float* fr = Freq + ((size_t)bh * 1025 + (2048 - r)) * Ss;
#pragma unroll
                    for (int nf = 0; nf < 8; nf++) {
                        int c0 = cbase + nf * 8;
                        acc[mf][nf][hf * 2]     += fr[(2048 - c0) & 2047];
                        acc[mf][nf][hf * 2 + 1] += fr[2047 - c0];
                    }
                }
            }

            float mx0 = -3.4e38f, mx1 = -3.4e38f;
#pragma unroll
            for (int nf = 0; nf < 8; nf++) {
                mx0 = fmaxf(mx0, fmaxf(acc[mf][nf][0], acc[mf][nf][1]));
                mx1 = fmaxf(mx1, fmaxf(acc[mf][nf][2], acc[mf][nf][3]));
            }
            mx0 = fmaxf(mx0, __shfl_xor_sync(0xffffffffu, mx0, 1));
            mx0 = fmaxf(mx0, __shfl_xor_sync(0xffffffffu, mx0, 2));
            mx1 = fmaxf(mx1, __shfl_xor_sync(0xffffffffu, mx1, 1));
            mx1 = fmaxf(mx1, __shfl_xor_sync(0xffffffffu, mx1, 2));

            float s0 = 0.f, s1 = 0.f;
#pragma unroll
            for (int nf = 0; nf < 8; nf++) {
                s0 += __expf(acc[mf][nf][0] - mx0) + __expf(acc[mf][nf][1] - mx0);
                s1 += __expf(acc[mf][nf][2] - mx1) + __expf(acc[mf][nf][3] - mx1);
            }
            s0 += __shfl_xor_sync(0xffffffffu, s0, 1);
            s0 += __shfl_xor_sync(0xffffffffu, s0, 2);
            s1 += __shfl_xor_sync(0xffffffffu, s1, 1);
            s1 += __shfl_xor_sync(0xffffffffu, s1, 2);

            if (tig == 0) {
                size_t gr0 = ((size_t)bh * Ss + row0) * NPART + ntile * 4 + wn;
                pmax[gr0] = mx0; psum[gr0] = s0;
                size_t gr1 = gr0 + 8 * NPART;
                pmax[gr1] = mx1; psum[gr1] = s1;
            }

            float* arow  = attn + ((size_t)bh << 22) + (size_t)row0 * Ss + cbase;
            float* arow8 = arow + 8 * Ss;
#pragma unroll
            for (int nf = 0; nf < 8; nf++)
                *(float2*)(arow + nf * 8) = make_float2(acc[mf][nf][0], acc[mf][nf][1]);
#pragma unroll
            for (int nf = 0; nf < 8; nf++)
                *(float2*)(arow8 + nf * 8) = make_float2(acc[mf][nf][2], acc[mf][nf][3]);
        }
    }
}

// ---------------------------------------------------------------------------
__global__ __launch_bounds__(256)
void combine_k(const float* __restrict__ pmax, const float* __restrict__ psum,
               float* __restrict__ rowm, float* __restrict__ rowz)
{
    int r = blockIdx.x * 256 + threadIdx.x;
    float m = -3.4e38f;
#pragma unroll
    for (int i = 0; i < NPART; i++) m = fmaxf(m, pmax[(size_t)r * NPART + i]);
    float z = 0.f;
#pragma unroll
    for (int i = 0; i < NPART; i++)
        z += psum[(size_t)r * NPART + i] * __expf(pmax[(size_t)r * NPART + i] - m);
    rowm[r] = m;
    rowz[r] = 1.f / z;
}

// ---------------------------------------------------------------------------
// Fused normalize + attn*V, single-fp16 V, no K-duplication. K=2048, 64 chunks.
// A: p fp16 [128 x 32/chunk], B: V [64 x 32/chunk]. Emits O ext fp16.
// ---------------------------------------------------------------------------
#define AVA (128 * 80)
#define AVB (64 * 80)

__global__ __launch_bounds__(256, 2)
void attnv16_k(float* __restrict__ attn, const __half* __restrict__ V16,
               const float* __restrict__ rowm, const float* __restrict__ rowz,
               __half* __restrict__ Oe)
{
    __shared__ char smc[2 * AVA + 2 * AVB];

    const int tid  = threadIdx.x;
    const int wid  = tid >> 5;
    const int lane = tid & 31;
    const int g    = lane >> 2;
    const int tig  = lane & 3;
    const int wm   = wid & 3;        // 4 m-strips of 32
    const int wn   = wid >> 2;       // 2 n-strips of 32

    const int mt = blockIdx.x, bh = blockIdx.y;
    const int m0 = mt * 128;
    float* Ab = attn + ((size_t)bh << 22) + (size_t)m0 * Ss;
    const __half* Vb = V16 + (size_t)bh * 64 * 2048;

    // prologue A: row = tid>>1 (128 rows), half-chunk = tid&1 (16 floats each)
    const int prow = tid >> 1;
    const int ph   = tid & 1;
    const float rm = rowm[bh * Ss + m0 + prow];
    const float rz = rowz[bh * Ss + m0 + prow];

    // prologue B: row = tid>>2 (64 rows), quarter = tid&3 (8 halfs each)
    const int brow = tid >> 2;
    const int bq   = tid & 3;

    float acc[2][4][4];
#pragma unroll
    for (int mf = 0; mf < 2; mf++)
#pragma unroll
        for (int nf = 0; nf < 4; nf++)
#pragma unroll
            for (int j = 0; j < 4; j++) acc[mf][nf][j] = 0.f;

    float4 pa[4];
    uint4  vb;

    auto ldg = [&](int c) {
#pragma unroll
        for (int i = 0; i < 4; i++)
            pa[i] = *(const float4*)(Ab + (size_t)prow * Ss + c * 32 + ph * 16 + i * 4);
        vb = *(const uint4*)(Vb + (size_t)brow * 2048 + c * 32 + bq * 8);
    };
    auto sts = [&](int b, int c) {
        char* a16 = smc + b * AVA;
        float p[16];
#pragma unroll
        for (int i = 0; i < 4; i++) {
            p[4*i+0] = __expf(pa[i].x - rm) * rz;
            p[4*i+1] = __expf(pa[i].y - rm) * rz;
            p[4*i+2] = __expf(pa[i].z - rm) * rz;
            p[4*i+3] = __expf(pa[i].w - rm) * rz;
            // writeback normalized attn (fp32, checked output)
            *(float4*)(Ab + (size_t)prow * Ss + c * 32 + ph * 16 + i * 4) =
                make_float4(p[4*i+0], p[4*i+1], p[4*i+2], p[4*i+3]);
        }
        uint4 h0;
        h0.x = packh2(__float2half_rn(p[0]),  __float2half_rn(p[1]));
        h0.y = packh2(__float2half_rn(p[2]),  __float2half_rn(p[3]));
        h0.z = packh2(__float2half_rn(p[4]),  __float2half_rn(p[5]));
        h0.w = packh2(__float2half_rn(p[6]),  __float2half_rn(p[7]));
        uint4 h1;
        h1.x = packh2(__float2half_rn(p[8]),  __float2half_rn(p[9]));
        h1.y = packh2(__float2half_rn(p[10]), __float2half_rn(p[11]));
        h1.z = packh2(__float2half_rn(p[12]), __float2half_rn(p[13]));
        h1.w = packh2(__float2half_rn(p[14]), __float2half_rn(p[15]));
        char* arow = a16 + prow * 80 + ph * 32;
        *(uint4*)(arow)      = h0;
        *(uint4*)(arow + 16) = h1;
        char* b16 = smc + 2 * AVA + b * AVB;
        *(uint4*)(b16 + brow * 80 + bq * 16) = vb;
    };

    ldg(0);
    sts(0, 0);
    __syncthreads();

    const int NCH = 64;   // 2048 / 32
    for (int c = 0; c < NCH; c++) {
        int buf = c & 1;
        if (c + 1 < NCH) ldg(c + 1);

        const char* a16 = smc + buf * AVA + (wm * 32) * 80;
        const char* b16 = smc + 2 * AVA + buf * AVB + (wn * 32) * 80;
#pragma unroll
        for (int st = 0; st < 2; st++) {
            int kb = st * 32;
            uint32_t bfr[4][2];
#pragma unroll
            for (int nf = 0; nf < 4; nf++) {
                const char* br = b16 + (nf * 8 + g) * 80 + kb + tig * 4;
                bfr[nf][0] = *(const uint32_t*)br;
                bfr[nf][1] = *(const uint32_t*)(br + 16);
            }
#pragma unroll
            for (int mf = 0; mf < 2; mf++) {
                const char* ar = a16 + (mf * 16 + g) * 80 + kb + tig * 4;
                uint32_t afr[4];
                afr[0] = *(const uint32_t*)ar;
                afr[1] = *(const uint32_t*)(ar + 8 * 80);
                afr[2] = *(const uint32_t*)(ar + 16);
                afr[3] = *(const uint32_t*)(ar + 8 * 80 + 16);
#pragma unroll
                for (int nf = 0; nf < 4; nf++)
                    mma_fp16(acc[mf][nf], afr, bfr[nf]);
            }
        }
        if (c + 1 < NCH) sts(buf ^ 1, c + 1);
        __syncthreads();
    }

    // epilogue: O -> ext fp16 [oh|ol|oh], row = b*2048+s, col = h*64+dk
    size_t rowbase = (size_t)(bh >> 4) * Ss + m0;
    int colbase = (bh & 15) * 64;
#pragma unroll
    for (int mf = 0; mf < 2; mf++) {
        int r0 = wm * 32 + mf * 16 + g;
#pragma unroll
        for (int nf = 0; nf < 4; nf++) {
            int col = colbase + wn * 32 + nf * 8 + tig * 2;
#pragma unroll
            for (int hf = 0; hf < 2; hf++) {
                float vx = acc[mf][nf][hf * 2], vy = acc[mf][nf][hf * 2 + 1];
                __half hx = __float2half_rn(vx), hy = __float2half_rn(vy);
                uint32_t H = packh2(hx, hy);
                uint32_t L = packh2(__float2half_rn(vx - __half2float(hx)),
                                    __float2half_rn(vy - __half2float(hy)));
                __half* orow = Oe + (rowbase + r0 + hf * 8) * XEXT;
                *(uint32_t*)(orow + col)        = H;
                *(uint32_t*)(orow + 1024 + col) = L;
                *(uint32_t*)(orow + 2048 + col) = H;
            }
        }
    }
}

// ---------------------------------------------------------------------------
extern "C" void kernel_launch(void* const* d_in, const int* in_sizes, int n_in,
                              void* d_out, int out_size)
{
    const float* x  = (const float*)d_in[0];
    const float* Wq = (const float*)d_in[1];
    const float* bq = (const float*)d_in[2];
    const float* Wk = (const float*)d_in[3];
    const float* bk = (const float*)d_in[4];
    const float* Wv = (const float*)d_in[5];
    const float* bv = (const float*)d_in[6];
    const float* Wo = (const float*)d_in[7];
    const float* bo = (const float*)d_in[8];
    const float* tw = (const float*)d_in[9];
    const float* fw = (const float*)d_in[10];

    float* out  = (float*)d_out;
    float* attn = out + (size_t)Mm * Dd;

    float *qaug, *kaug, *freq, *pmax, *psum, *rowm, *rowz;
    __half *qe, *ke, *v16, *xe, *oe;
    cudaGetSymbolAddress((void**)&qaug, g_Qaug);
    cudaGetSymbolAddress((void**)&kaug, g_Kaug);
    cudaGetSymbolAddress((void**)&qe,   g_Qe16);
    cudaGetSymbolAddress((void**)&ke,   g_Ke16);
    cudaGetSymbolAddress((void**)&v16,  g_V16);
    cudaGetSymbolAddress((void**)&freq, g_Freq);
    cudaGetSymbolAddress((void**)&xe,   g_Xext);
    cudaGetSymbolAddress((void**)&oe,   g_Oext);
    cudaGetSymbolAddress((void**)&pmax, g_pmax);
    cudaGetSymbolAddress((void**)&psum, g_psum);
    cudaGetSymbolAddress((void**)&rowm, g_rowm);
    cudaGetSymbolAddress((void**)&rowz, g_rowz);

    static const int SM16 = 2 * A16B + 2 * B16B;   // 61440
    cudaFuncSetAttribute(scores16_k<192, 12, 0>,
                         cudaFuncAttributeMaxDynamicSharedMemorySize, SM16);
    cudaFuncSetAttribute(scores16_k<0, 6, 1>,
                         cudaFuncAttributeMaxDynamicSharedMemorySize, SM16);
    cudaFuncSetAttribute(gemm16qkv_k, cudaFuncAttributeMaxDynamicSharedMemorySize, SM16);
    cudaFuncSetAttribute(gemm16o_k,   cudaFuncAttributeMaxDynamicSharedMemorySize, SM16);

    dim3 blk(256);

    twiddle_init_k<<<4, 256>>>();

    // ext conversions
    convx_k<<<Mm, 256>>>(x, xe);
    convw_k<<<dim3(Dd, 4), 256>>>(Wq, Wk, Wv, Wo);

    // merged Q/K/V projections (fp16 3-term)
    gemm16qkv_k<<<dim3(4, 32, 3), blk, SM16>>>(xe, bq, bk, bv, qaug, kaug, v16);

    // FFT
    fft_k<<<dim3(BHh, 2, 32), blk>>>(qaug, kaug, tw, fw);

    // fp16x2 split for scores
    {
        int nblk = (int)(((size_t)BHh * Ss * 48) / 256);
        convert16_k<1><<<nblk, 256>>>(qaug, qe);
        convert16_k<0><<<nblk, 256>>>(kaug, ke);
    }

    // freq scores rows 0..1024 -> staged
    scores16_k<192, 12, 0><<<dim3(8, 9, BHh), blk, SM16>>>(qe, ke, attn, freq, pmax, psum);

    // time scores + freq add + softmax partials
    scores16_k<0, 6, 1><<<dim3(8, 16, BHh), blk, SM16>>>(qe, ke, attn, freq, pmax, psum);

    // combine partials
    combine_k<<<(BHh * Ss) / 256, 256>>>(pmax, psum, rowm, rowz);

    // fused normalize + attn*V (single-fp16 V, K=2048)
    attnv16_k<<<dim3(16, BHh), blk>>>(attn, v16, rowm, rowz, oe);

    // out projection
    gemm16o_k<<<dim3(4, 32), blk, SM16>>>(oe, bo, out);
}